// round 11
// baseline (speedup 1.0000x reference)
#include <cuda_runtime.h>
#include <math.h>
#include <stdint.h>

// ---------------- problem constants ----------------
#define B_ 2
#define E_ 256
#define NH_ 8
#define NL_ 4
#define NP_ 4
#define DF_ 1024
#define NLAYERS_ 6
#define HD_ 32
#define S_ 10548
#define M_ (B_*S_)          // 21096 query rows

__device__ __constant__ int c_LD[4] = {4, 2, 1, 1};
__device__ __constant__ int c_LH[4] = {48, 24, 12, 6};
__device__ __constant__ int c_LW[4] = {48, 24, 12, 6};

// ---------------- scratch (allocation-free) ----------------
__device__ float g_x  [M_*E_];
__device__ float g_xr [M_*E_];
__device__ float g_pos[M_*E_];
__device__ float g_q  [M_*E_];
__device__ float g_val[M_*E_];
__device__ float g_sam[M_*E_];
__device__ float g_tmp[M_*E_];
__device__ float g_oa [M_*512];    // packed: [0,384) offsets, [384,512) attn logits
__device__ float g_hid[M_*DF_];

// pre-rounded packed weights [K,N] row-major
__device__ float g_Wval[NLAYERS_*E_*E_];
__device__ float g_Wqa [NLAYERS_*E_*512];
__device__ float g_Wout[NLAYERS_*E_*E_];
__device__ float g_Wff1[NLAYERS_*E_*DF_];
__device__ float g_Wff2[NLAYERS_*DF_*E_];
__device__ float g_bqa [NLAYERS_*512];

// ---------------- tf32 helpers ----------------
__device__ __forceinline__ unsigned tf32_bits(float x)
{
    unsigned r;
    asm("cvt.rna.tf32.f32 %0, %1;\n" : "=r"(r) : "f"(x));
    return r;
}
__device__ __forceinline__ float tf32_round(float x)
{
    return __uint_as_float(tf32_bits(x));
}

__device__ __forceinline__ void mma_tf32(float c[4], const unsigned a[4], const unsigned b[2])
{
    asm volatile("mma.sync.aligned.m16n8k8.row.col.f32.tf32.tf32.f32 "
        "{%0,%1,%2,%3}, {%4,%5,%6,%7}, {%8,%9}, {%0,%1,%2,%3};\n"
        : "+f"(c[0]), "+f"(c[1]), "+f"(c[2]), "+f"(c[3])
        : "r"(a[0]), "r"(a[1]), "r"(a[2]), "r"(a[3]), "r"(b[0]), "r"(b[1]));
}

__device__ __forceinline__ void cp_async16(void* smem, const void* gmem, bool valid)
{
    unsigned saddr = (unsigned)__cvta_generic_to_shared(smem);
    int sz = valid ? 16 : 0;
    asm volatile("cp.async.cg.shared.global [%0], [%1], 16, %2;\n"
                 :: "r"(saddr), "l"(gmem), "r"(sz));
}
__device__ __forceinline__ void cp_commit() { asm volatile("cp.async.commit_group;\n"); }
template<int N> __device__ __forceinline__ void cp_wait() { asm volatile("cp.async.wait_group %0;\n" :: "n"(N)); }

#define LDSM_X4(r0,r1,r2,r3,addr) \
    asm volatile("ldmatrix.sync.aligned.m8n8.x4.shared.b16 {%0,%1,%2,%3}, [%4];\n" \
        : "=r"(r0), "=r"(r1), "=r"(r2), "=r"(r3) : "r"(addr))

// ---------------- merged weight prep (single launch) ----------------
__global__ void prep_weights(const float* __restrict__ W_val, const float* __restrict__ W_out,
                             const float* __restrict__ W_ff1, const float* __restrict__ W_ff2,
                             const float* __restrict__ W_off, const float* __restrict__ W_attn,
                             const float* __restrict__ b_off, const float* __restrict__ b_attn)
{
    const int nVal = NLAYERS_*E_*E_;     // 393216
    const int nFf  = NLAYERS_*E_*DF_;    // 1572864
    const int nQa  = NLAYERS_*E_*512;    // 786432
    int i = blockIdx.x * blockDim.x + threadIdx.x;
    if (i < nVal) { g_Wval[i] = tf32_round(W_val[i]); return; }
    i -= nVal;
    if (i < nVal) { g_Wout[i] = tf32_round(W_out[i]); return; }
    i -= nVal;
    if (i < nFf)  { g_Wff1[i] = tf32_round(W_ff1[i]); return; }
    i -= nFf;
    if (i < nFf)  { g_Wff2[i] = tf32_round(W_ff2[i]); return; }
    i -= nFf;
    if (i < nQa) {
        int l = i / (E_ * 512);
        int rem = i - l * E_ * 512;
        int k = rem >> 9;
        int c = rem & 511;
        float v = (c < 384) ? W_off[(size_t)l*E_*384 + k*384 + c]
                            : W_attn[(size_t)l*E_*128 + k*128 + (c - 384)];
        g_Wqa[i] = tf32_round(v);
        return;
    }
    i -= nQa;
    if (i < NLAYERS_ * 512) {
        int l = i >> 9;
        int c = i & 511;
        g_bqa[i] = (c < 384) ? b_off[l*384 + c] : b_attn[l*128 + (c - 384)];
    }
}
#define PREP_TOT (2*NLAYERS_*E_*E_ + 2*NLAYERS_*E_*DF_ + NLAYERS_*E_*512 + NLAYERS_*512)

// ---------------- coalesced transposing init (per level) ----------------
__global__ void init_t_kernel(const float* __restrict__ f, const float* __restrict__ p,
                              const float* __restrict__ le_row, int n, int s0)
{
    __shared__ float tf[32][33];
    __shared__ float tp[32][33];
    int i0 = blockIdx.x * 32;
    int e0 = blockIdx.y * 32;
    int b  = blockIdx.z;
    int tx = threadIdx.x, ty = threadIdx.y;

    int ig = i0 + tx;
    int eg = e0 + ty;
    if (ig < n) {
        size_t src = (size_t)(b*E_ + eg) * n + ig;
        tf[ty][tx] = f[src];
        tp[ty][tx] = p[src];
    }
    __syncthreads();

    int iw = i0 + ty;
    int ew = e0 + tx;
    if (iw < n) {
        size_t dst = (size_t)(b*S_ + s0 + iw) * E_ + ew;
        float xv = tf[tx][ty];
        float pv = tp[tx][ty] + le_row[ew];
        g_x[dst]   = xv;
        g_xr[dst]  = tf32_round(xv);
        g_pos[dst] = pv;
        g_q[dst]   = tf32_round(xv + pv);
    }
}

// ---------------- tf32 tensor-core GEMM body (shared by kernels) ----------
template<int BMt, int BNt>
__device__ __forceinline__ void gemm_body(
    const float* __restrict__ A, const float* __restrict__ W,
    const float* __restrict__ bias, float* __restrict__ C,
    int M, int N, int K, int mode, float* smp)
{
    constexpr int MI   = BMt/32;
    constexpr int NI   = BNt/32;
    constexpr int ACH  = BMt/32;
    constexpr int BCH  = BNt/32;
    constexpr int CPR  = BNt/4;
    constexpr int ASTR = 36;
    constexpr int BSTR = BNt + 8;
    constexpr int A_FL = BMt*ASTR;
    constexpr int B_FL = 32*BSTR;
    constexpr int STG  = A_FL + B_FL;

    int tid  = threadIdx.x;
    int lane = tid & 31;
    int wid  = tid >> 5;
    int bm = blockIdx.y * BMt;
    int bn = blockIdx.x * BNt;
    int wm = (wid >> 2) * (BMt/2);
    int wn = (wid & 3) * (BNt/4);
    int q = lane >> 2;
    int r = lane & 3;

    float acc[MI][NI][4];
    #pragma unroll
    for (int mi = 0; mi < MI; mi++)
        #pragma unroll
        for (int ni = 0; ni < NI; ni++)
            #pragma unroll
            for (int j = 0; j < 4; j++) acc[mi][ni][j] = 0.f;

    int arow[ACH], ac[ACH]; bool aval[ACH];
    #pragma unroll
    for (int i = 0; i < ACH; i++) {
        int idx = tid + i*256; arow[i] = idx >> 3; ac[i] = idx & 7;
        aval[i] = (bm + arow[i]) < M;
    }
    int brow[BCH], bc[BCH];
    #pragma unroll
    for (int i = 0; i < BCH; i++) { int idx = tid + i*256; brow[i] = idx / CPR; bc[i] = idx % CPR; }

    int nkt = K / 32;

    int mt = lane >> 3;
    int rbase = (mt & 1)*8 + (lane & 7);
    int koff = (mt >> 1)*4;
    unsigned smem_u32 = (unsigned)__cvta_generic_to_shared(smp);

    {
        float* As = smp;
        float* Bs = smp + A_FL;
        #pragma unroll
        for (int i = 0; i < ACH; i++)
            cp_async16(As + arow[i]*ASTR + ac[i]*4,
                       A + (size_t)(aval[i] ? (bm + arow[i]) : 0) * K + ac[i]*4, aval[i]);
        #pragma unroll
        for (int i = 0; i < BCH; i++)
            cp_async16(Bs + brow[i]*BSTR + bc[i]*4,
                       W + (size_t)brow[i] * N + bn + bc[i]*4, true);
        cp_commit();
        if (nkt > 1) {
            float* As1 = smp + STG;
            float* Bs1 = As1 + A_FL;
            #pragma unroll
            for (int i = 0; i < ACH; i++)
                cp_async16(As1 + arow[i]*ASTR + ac[i]*4,
                           A + (size_t)(aval[i] ? (bm + arow[i]) : 0) * K + 32 + ac[i]*4, aval[i]);
            #pragma unroll
            for (int i = 0; i < BCH; i++)
                cp_async16(Bs1 + brow[i]*BSTR + bc[i]*4,
                           W + (size_t)(32 + brow[i]) * N + bn + bc[i]*4, true);
        }
        cp_commit();
    }

    for (int kt = 0; kt < nkt; kt++) {
        int st = kt % 3;
        if (kt + 2 < nkt) {
            int s2 = (kt + 2) % 3;
            float* As = smp + s2*STG;
            float* Bs = As + A_FL;
            int kg = (kt + 2) * 32;
            #pragma unroll
            for (int i = 0; i < ACH; i++)
                cp_async16(As + arow[i]*ASTR + ac[i]*4,
                           A + (size_t)(aval[i] ? (bm + arow[i]) : 0) * K + kg + ac[i]*4, aval[i]);
            #pragma unroll
            for (int i = 0; i < BCH; i++)
                cp_async16(Bs + brow[i]*BSTR + bc[i]*4,
                           W + (size_t)(kg + brow[i]) * N + bn + bc[i]*4, true);
        }
        cp_commit();
        cp_wait<2>();
        __syncthreads();

        const float* Bs = smp + st*STG + A_FL;
        unsigned abase = smem_u32 + (unsigned)(st*STG)*4u
                       + (unsigned)((wm + rbase)*ASTR + koff)*4u;

        #pragma unroll
        for (int ks = 0; ks < 4; ks++) {
            unsigned af[MI][4], bf[NI][2];
            #pragma unroll
            for (int mi = 0; mi < MI; mi++) {
                LDSM_X4(af[mi][0], af[mi][1], af[mi][2], af[mi][3],
                        abase + (unsigned)((mi*16*ASTR + ks*8)*4));
            }
            #pragma unroll
            for (int ni = 0; ni < NI; ni++) {
                bf[ni][0] = __float_as_uint(Bs[(ks*8 + r    )*BSTR + wn + ni*8 + q]);
                bf[ni][1] = __float_as_uint(Bs[(ks*8 + r + 4)*BSTR + wn + ni*8 + q]);
            }
            #pragma unroll
            for (int mi = 0; mi < MI; mi++)
                #pragma unroll
                for (int ni = 0; ni < NI; ni++)
                    mma_tf32(acc[mi][ni], af[mi], bf[ni]);
        }
        __syncthreads();
    }

    #pragma unroll
    for (int mi = 0; mi < MI; mi++) {
        #pragma unroll
        for (int ni = 0; ni < NI; ni++) {
            int row = bm + wm + mi*16 + q;
            int col = bn + wn + ni*8 + r*2;
            float bx = bias[col], by = bias[col+1];
            if (row < M) {
                float v0 = acc[mi][ni][0] + bx;
                float v1 = acc[mi][ni][1] + by;
                if (mode == 1) { v0 = tf32_round(fmaxf(v0, 0.f)); v1 = tf32_round(fmaxf(v1, 0.f)); }
                *(float2*)&C[(size_t)row * N + col] = make_float2(v0, v1);
            }
            if (row + 8 < M) {
                float v2 = acc[mi][ni][2] + bx;
                float v3 = acc[mi][ni][3] + by;
                if (mode == 1) { v2 = tf32_round(fmaxf(v2, 0.f)); v3 = tf32_round(fmaxf(v3, 0.f)); }
                *(float2*)&C[(size_t)(row + 8) * N + col] = make_float2(v2, v3);
            }
        }
    }
}

template<int BMt, int BNt>
__global__ void __launch_bounds__(256, (BMt==64 ? 4 : 2))
mma_gemm(const float* __restrict__ A, const float* __restrict__ W,
         const float* __restrict__ bias, float* __restrict__ C,
         int M, int N, int K, int mode)
{
    extern __shared__ float smp[];
    gemm_body<BMt, BNt>(A, W, bias, C, M, N, K, mode, smp);
}

// batched dual GEMM: z=0 -> (A0,W0,b0,C0,N0), z=1 -> (A1,W1,b1,C1,N1); 64x64 tiles
__global__ void __launch_bounds__(256, 4)
mma_gemm_dual(const float* __restrict__ A0, const float* __restrict__ W0,
              const float* __restrict__ b0, float* __restrict__ C0, int N0,
              const float* __restrict__ A1, const float* __restrict__ W1,
              const float* __restrict__ b1, float* __restrict__ C1, int N1,
              int M, int K)
{
    extern __shared__ float smp[];
    if (blockIdx.z == 0) {
        if ((int)blockIdx.x * 64 >= N0) return;
        gemm_body<64,64>(A0, W0, b0, C0, M, N0, K, 0, smp);
    } else {
        gemm_body<64,64>(A1, W1, b1, C1, M, N1, K, 0, smp);
    }
}

// ---------------- deformable sampling, float4-vectorized ----------------
__global__ void sample_kernel()
{
    int warpIdx = (blockIdx.x * blockDim.x + threadIdx.x) >> 5;
    int lane  = threadIdx.x & 31;
    if (warpIdx >= M_ * NH_) return;
    int h  = warpIdx / M_;
    int bs = warpIdx - h * M_;
    int b  = bs / S_;
    int s  = bs % S_;
    int eg = lane & 7;
    int pg = lane >> 3;

    int lvl_q, iq;
    if (s < 9216)       { lvl_q = 0; iq = s;         }
    else if (s < 10368) { lvl_q = 1; iq = s - 9216;  }
    else if (s < 10512) { lvl_q = 2; iq = s - 10368; }
    else                { lvl_q = 3; iq = s - 10512; }
    int Wq = c_LW[lvl_q], Hq = c_LH[lvl_q], Dq = c_LD[lvl_q];
    int xq = iq % Wq;
    int t  = iq / Wq;
    int yq = t % Hq;
    int zq = t / Hq;
    float rx = (xq + 0.5f) / (float)Wq;
    float ry = (yq + 0.5f) / (float)Hq;
    float rz = (zq + 0.5f) / (float)Dq;

    const float4* lg4 = (const float4*)(g_oa + (size_t)bs * 512 + 384 + h * 16);
    float lv[16];
    {
        float4 v0 = lg4[0], v1 = lg4[1], v2 = lg4[2], v3 = lg4[3];
        lv[0]=v0.x; lv[1]=v0.y; lv[2]=v0.z; lv[3]=v0.w;
        lv[4]=v1.x; lv[5]=v1.y; lv[6]=v1.z; lv[7]=v1.w;
        lv[8]=v2.x; lv[9]=v2.y; lv[10]=v2.z; lv[11]=v2.w;
        lv[12]=v3.x; lv[13]=v3.y; lv[14]=v3.z; lv[15]=v3.w;
    }
    float mx = -1e30f;
    #pragma unroll
    for (int j = 0; j < 16; j++) mx = fmaxf(mx, lv[j]);
    float ssum = 0.f;
    #pragma unroll
    for (int j = 0; j < 16; j++) { lv[j] = __expf(lv[j] - mx); ssum += lv[j]; }
    float inv = 1.f / ssum;

    const float* offp = g_oa + (size_t)bs * 512 + h * (NL_*NP_*3);

    const int LDc[4]  = {4, 2, 1, 1};
    const int LHc[4]  = {48, 24, 12, 6};
    const int LWc[4]  = {48, 24, 12, 6};
    const int LS0c[4] = {0, 9216, 10368, 10512};

    float4 acc = make_float4(0.f, 0.f, 0.f, 0.f);

    #pragma unroll
    for (int lvl = 0; lvl < 4; lvl++) {
        const int Dl = LDc[lvl], Hl = LHc[lvl], Wl = LWc[lvl];
        const float* vb = g_val + ((size_t)b * S_ + LS0c[lvl]) * E_ + h * HD_ + eg * 4;

        float aw = lv[lvl*4 + pg] * inv;
        float ox = offp[lvl*12 + pg*3 + 0];
        float oy = offp[lvl*12 + pg*3 + 1];
        float oz = offp[lvl*12 + pg*3 + 2];
        float cx = rx * (float)Wl + ox - 0.5f;
        float cy = ry * (float)Hl + oy - 0.5f;
        float cz = rz * (float)Dl + oz - 0.5f;
        float xf = floorf(cx), yf = floorf(cy), zf = floorf(cz);
        float fx = cx - xf, fy = cy - yf, fz = cz - zf;
        int x0 = (int)xf, y0 = (int)yf, z0 = (int)zf;

        #pragma unroll
        for (int dz = 0; dz < 2; dz++) {
            int iz = z0 + dz;
            float wz = dz ? fz : 1.f - fz;
            bool vz = (iz >= 0) & (iz < Dl);
            int cz_i = min(max(iz, 0), Dl - 1);
            #pragma unroll
            for (int dy = 0; dy < 2; dy++) {
                int iy = y0 + dy;
                float wy = dy ? fy : 1.f - fy;
                bool vy = (iy >= 0) & (iy < Hl);
                int cy_i = min(max(iy, 0), Hl - 1);
                #pragma unroll
                for (int dx = 0; dx < 2; dx++) {
                    int ix = x0 + dx;
                    float wx = dx ? fx : 1.f - fx;
                    bool vx = (ix >= 0) & (ix < Wl);
                    int cx_i = min(max(ix, 0), Wl - 1);
                    float wgt = (vz & vy & vx) ? (aw * wx * wy * wz) : 0.f;
                    int idx = (cz_i*Hl + cy_i)*Wl + cx_i;
                    float4 v = *(const float4*)(vb + (size_t)idx * E_);
                    acc.x += wgt * v.x;
                    acc.y += wgt * v.y;
                    acc.z += wgt * v.z;
                    acc.w += wgt * v.w;
                }
            }
        }
    }

    #pragma unroll
    for (int o = 8; o <= 16; o <<= 1) {
        acc.x += __shfl_xor_sync(0xFFFFFFFFu, acc.x, o);
        acc.y += __shfl_xor_sync(0xFFFFFFFFu, acc.y, o);
        acc.z += __shfl_xor_sync(0xFFFFFFFFu, acc.z, o);
        acc.w += __shfl_xor_sync(0xFFFFFFFFu, acc.w, o);
    }

    if (lane < 8) {
        float4 o4;
        o4.x = tf32_round(acc.x);
        o4.y = tf32_round(acc.y);
        o4.z = tf32_round(acc.z);
        o4.w = tf32_round(acc.w);
        *(float4*)(g_sam + (size_t)bs * E_ + h * HD_ + lane * 4) = o4;
    }
}

// ---------------- fused residual + LayerNorm: warp-per-row, 8 rows/block ----
__global__ void __launch_bounds__(256)
ln8_kernel(const float* __restrict__ x, const float* __restrict__ r,
           const float* __restrict__ g, const float* __restrict__ be,
           float* __restrict__ out, float* __restrict__ outr,
           const float* __restrict__ pos, float* __restrict__ qout)
{
    int wid  = threadIdx.x >> 5;
    int lane = threadIdx.x & 31;
    int row  = blockIdx.x * 8 + wid;   // M_ = 21096 = 2637 * 8
    size_t base = (size_t)row * E_;
    int c0 = lane * 4;
    int c1 = 128 + lane * 4;

    float4 xa = *(const float4*)(x + base + c0);
    float4 xb = *(const float4*)(x + base + c1);
    float4 ra = *(const float4*)(r + base + c0);
    float4 rb = *(const float4*)(r + base + c1);
    float4 va = make_float4(xa.x+ra.x, xa.y+ra.y, xa.z+ra.z, xa.w+ra.w);
    float4 vb = make_float4(xb.x+rb.x, xb.y+rb.y, xb.z+rb.z, xb.w+rb.w);

    float ssum = va.x+va.y+va.z+va.w + vb.x+vb.y+vb.z+vb.w;
    #pragma unroll
    for (int o = 16; o > 0; o >>= 1) ssum += __shfl_xor_sync(0xFFFFFFFFu, ssum, o);
    float mean = ssum * (1.f / E_);

    float4 da = make_float4(va.x-mean, va.y-mean, va.z-mean, va.w-mean);
    float4 db = make_float4(vb.x-mean, vb.y-mean, vb.z-mean, vb.w-mean);
    float vsum = da.x*da.x+da.y*da.y+da.z*da.z+da.w*da.w
               + db.x*db.x+db.y*db.y+db.z*db.z+db.w*db.w;
    #pragma unroll
    for (int o = 16; o > 0; o >>= 1) vsum += __shfl_xor_sync(0xFFFFFFFFu, vsum, o);
    float inv = rsqrtf(vsum * (1.f / E_) + 1e-5f);

    float4 ga = *(const float4*)(g + c0);
    float4 gb = *(const float4*)(g + c1);
    float4 ba = *(const float4*)(be + c0);
    float4 bb = *(const float4*)(be + c1);

    float4 ya = make_float4(da.x*inv*ga.x + ba.x, da.y*inv*ga.y + ba.y,
                            da.z*inv*ga.z + ba.z, da.w*inv*ga.w + ba.w);
    float4 yb = make_float4(db.x*inv*gb.x + bb.x, db.y*inv*gb.y + bb.y,
                            db.z*inv*gb.z + bb.z, db.w*inv*gb.w + bb.w);

    *(float4*)(out + base + c0) = ya;
    *(float4*)(out + base + c1) = yb;

    if (outr) {
        float4 wa = make_float4(tf32_round(ya.x), tf32_round(ya.y),
                                tf32_round(ya.z), tf32_round(ya.w));
        float4 wb = make_float4(tf32_round(yb.x), tf32_round(yb.y),
                                tf32_round(yb.z), tf32_round(yb.w));
        *(float4*)(outr + base + c0) = wa;
        *(float4*)(outr + base + c1) = wb;
    }
    if (qout) {
        float4 pa = *(const float4*)(pos + base + c0);
        float4 pb = *(const float4*)(pos + base + c1);
        float4 qa = make_float4(tf32_round(ya.x + pa.x), tf32_round(ya.y + pa.y),
                                tf32_round(ya.z + pa.z), tf32_round(ya.w + pa.w));
        float4 qb = make_float4(tf32_round(yb.x + pb.x), tf32_round(yb.y + pb.y),
                                tf32_round(yb.z + pb.z), tf32_round(yb.w + pb.w));
        *(float4*)(qout + base + c0) = qa;
        *(float4*)(qout + base + c1) = qb;
    }
}

// ---------------- host launcher ----------------
#define SMEM128 (3*(128*36 + 32*136)*4)
#define SMEM64  (3*(64*36 + 32*72)*4)

extern "C" void kernel_launch(void* const* d_in, const int* in_sizes, int n_in,
                              void* d_out, int out_size)
{
    (void)in_sizes; (void)n_in; (void)out_size;
    const float* f0 = (const float*)d_in[0];
    const float* p0 = (const float*)d_in[1];
    const float* f1 = (const float*)d_in[2];
    const float* p1 = (const float*)d_in[3];
    const float* f2 = (const float*)d_in[4];
    const float* p2 = (const float*)d_in[5];
    const float* f3 = (const float*)d_in[6];
    const float* p3 = (const float*)d_in[7];
    const float* le = (const float*)d_in[8];
    const float* W_off  = (const float*)d_in[9];
    const float* b_off  = (const float*)d_in[10];
    const float* W_attn = (const float*)d_in[11];
    const float* b_attn = (const float*)d_in[12];
    const float* W_val  = (const float*)d_in[13];
    const float* b_val  = (const float*)d_in[14];
    const float* W_out  = (const float*)d_in[15];
    const float* b_out  = (const float*)d_in[16];
    const float* ln1_g  = (const float*)d_in[17];
    const float* ln1_b  = (const float*)d_in[18];
    const float* W_ff1  = (const float*)d_in[19];
    const float* b_ff1  = (const float*)d_in[20];
    const float* W_ff2  = (const float*)d_in[21];
    const float* b_ff2  = (const float*)d_in[22];
    const float* ln2_g  = (const float*)d_in[23];
    const float* ln2_b  = (const float*)d_in[24];

    float *px, *pxr, *ppos, *pq, *pval, *psam, *ptmp, *phid, *poa;
    float *pWval, *pWqa, *pWout, *pWff1, *pWff2, *pbqa;
    cudaGetSymbolAddress((void**)&px,    g_x);
    cudaGetSymbolAddress((void**)&pxr,   g_xr);
    cudaGetSymbolAddress((void**)&ppos,  g_pos);
    cudaGetSymbolAddress((void**)&pq,    g_q);
    cudaGetSymbolAddress((void**)&pval,  g_val);
    cudaGetSymbolAddress((void**)&psam,  g_sam);
    cudaGetSymbolAddress((void**)&ptmp,  g_tmp);
    cudaGetSymbolAddress((void**)&phid,  g_hid);
    cudaGetSymbolAddress((void**)&poa,   g_oa);
    cudaGetSymbolAddress((void**)&pWval, g_Wval);
    cudaGetSymbolAddress((void**)&pWqa,  g_Wqa);
    cudaGetSymbolAddress((void**)&pWout, g_Wout);
    cudaGetSymbolAddress((void**)&pWff1, g_Wff1);
    cudaGetSymbolAddress((void**)&pWff2, g_Wff2);
    cudaGetSymbolAddress((void**)&pbqa,  g_bqa);

    cudaFuncSetAttribute(mma_gemm<128,128>, cudaFuncAttributeMaxDynamicSharedMemorySize, SMEM128);
    cudaFuncSetAttribute(mma_gemm<64,64>,   cudaFuncAttributeMaxDynamicSharedMemorySize, SMEM64);
    cudaFuncSetAttribute(mma_gemm_dual,     cudaFuncAttributeMaxDynamicSharedMemorySize, SMEM64);

    // launch 1: merged weight prep
    prep_weights<<<(PREP_TOT + 255)/256, 256>>>(W_val, W_out, W_ff1, W_ff2,
                                                W_off, W_attn, b_off, b_attn);

    // launches 2-5: transposing init, one per level
    {
        dim3 blk(32, 32);
        init_t_kernel<<<dim3(288, 8, B_), blk>>>(f0, p0, le + 0*E_, 9216, 0);
        init_t_kernel<<<dim3( 36, 8, B_), blk>>>(f1, p1, le + 1*E_, 1152, 9216);
        init_t_kernel<<<dim3(  5, 8, B_), blk>>>(f2, p2, le + 2*E_,  144, 10368);
        init_t_kernel<<<dim3(  2, 8, B_), blk>>>(f3, p3, le + 3*E_,   36, 10512);
    }

    const int GM64  = (M_ + 63) / 64;    // 330
    const int GM128 = (M_ + 127) / 128;  // 165
    const int LNB   = M_ / 8;            // 2637

    for (int l = 0; l < NLAYERS_; l++) {
        // launch 6 (layer 0): batched val + qa GEMM -> ncu captures this one
        mma_gemm_dual<<<dim3(8, GM64, 2), 256, SMEM64>>>(
            pxr, pWval + (size_t)l*E_*E_,  b_val + l*E_, pval, E_,
            pq,  pWqa  + (size_t)l*E_*512, pbqa + l*512, poa, 512,
            M_, E_);

        sample_kernel<<<(M_ * NH_ * 32) / 256, 256>>>();

        mma_gemm<64,64><<<dim3(E_/64, GM64), 256, SMEM64>>>(psam, pWout + (size_t)l*E_*E_,
                                           b_out + l*E_, ptmp, M_, E_, E_, 0);
        ln8_kernel<<<LNB, 256>>>(px, ptmp, ln1_g + l*E_, ln1_b + l*E_, px, pxr,
                                 (const float*)0, (float*)0);

        mma_gemm<128,128><<<dim3(DF_/128, GM128), 256, SMEM128>>>(pxr, pWff1 + (size_t)l*E_*DF_,
                                            b_ff1 + l*DF_, phid, M_, DF_, E_, 1);
        mma_gemm<64,64><<<dim3(E_/64, GM64), 256, SMEM64>>>(phid, pWff2 + (size_t)l*DF_*E_,
                                           b_ff2 + l*E_, ptmp, M_, E_, DF_, 0);

        if (l == NLAYERS_ - 1) {
            ln8_kernel<<<LNB, 256>>>(px, ptmp, ln2_g + l*E_, ln2_b + l*E_,
                                     (float*)d_out, (float*)0, (const float*)0, (float*)0);
        } else {
            ln8_kernel<<<LNB, 256>>>(px, ptmp, ln2_g + l*E_, ln2_b + l*E_,
                                     px, pxr, ppos, pq);
        }
    }
}

// round 12
// speedup vs baseline: 1.0298x; 1.0298x over previous
#include <cuda_runtime.h>
#include <cuda_fp16.h>
#include <math.h>
#include <stdint.h>

// ---------------- problem constants ----------------
#define B_ 2
#define E_ 256
#define NH_ 8
#define NL_ 4
#define NP_ 4
#define DF_ 1024
#define NLAYERS_ 6
#define HD_ 32
#define S_ 10548
#define M_ (B_*S_)          // 21096 query rows

__device__ __constant__ int c_LD[4] = {4, 2, 1, 1};
__device__ __constant__ int c_LH[4] = {48, 24, 12, 6};
__device__ __constant__ int c_LW[4] = {48, 24, 12, 6};

// ---------------- scratch (allocation-free) ----------------
__device__ float  g_x  [M_*E_];
__device__ float  g_xr [M_*E_];
__device__ float  g_pos[M_*E_];
__device__ float  g_q  [M_*E_];
__device__ __half g_valh[M_*E_];   // fp16 value tensor (halves sampler L1 traffic)
__device__ float  g_sam[M_*E_];
__device__ float  g_tmp[M_*E_];
__device__ float  g_oa [M_*512];   // packed: [0,384) offsets, [384,512) attn logits
__device__ float  g_hid[M_*DF_];

// pre-rounded packed weights [K,N] row-major
__device__ float g_Wval[NLAYERS_*E_*E_];
__device__ float g_Wqa [NLAYERS_*E_*512];
__device__ float g_Wout[NLAYERS_*E_*E_];
__device__ float g_Wff1[NLAYERS_*E_*DF_];
__device__ float g_Wff2[NLAYERS_*DF_*E_];
__device__ float g_bqa [NLAYERS_*512];

// ---------------- tf32 helpers ----------------
__device__ __forceinline__ unsigned tf32_bits(float x)
{
    unsigned r;
    asm("cvt.rna.tf32.f32 %0, %1;\n" : "=r"(r) : "f"(x));
    return r;
}
__device__ __forceinline__ float tf32_round(float x)
{
    return __uint_as_float(tf32_bits(x));
}

__device__ __forceinline__ void mma_tf32(float c[4], const unsigned a[4], const unsigned b[2])
{
    asm volatile("mma.sync.aligned.m16n8k8.row.col.f32.tf32.tf32.f32 "
        "{%0,%1,%2,%3}, {%4,%5,%6,%7}, {%8,%9}, {%0,%1,%2,%3};\n"
        : "+f"(c[0]), "+f"(c[1]), "+f"(c[2]), "+f"(c[3])
        : "r"(a[0]), "r"(a[1]), "r"(a[2]), "r"(a[3]), "r"(b[0]), "r"(b[1]));
}

__device__ __forceinline__ void cp_async16(void* smem, const void* gmem, bool valid)
{
    unsigned saddr = (unsigned)__cvta_generic_to_shared(smem);
    int sz = valid ? 16 : 0;
    asm volatile("cp.async.cg.shared.global [%0], [%1], 16, %2;\n"
                 :: "r"(saddr), "l"(gmem), "r"(sz));
}
__device__ __forceinline__ void cp_commit() { asm volatile("cp.async.commit_group;\n"); }
template<int N> __device__ __forceinline__ void cp_wait() { asm volatile("cp.async.wait_group %0;\n" :: "n"(N)); }

#define LDSM_X4(r0,r1,r2,r3,addr) \
    asm volatile("ldmatrix.sync.aligned.m8n8.x4.shared.b16 {%0,%1,%2,%3}, [%4];\n" \
        : "=r"(r0), "=r"(r1), "=r"(r2), "=r"(r3) : "r"(addr))

// ---------------- merged weight prep (single launch) ----------------
__global__ void prep_weights(const float* __restrict__ W_val, const float* __restrict__ W_out,
                             const float* __restrict__ W_ff1, const float* __restrict__ W_ff2,
                             const float* __restrict__ W_off, const float* __restrict__ W_attn,
                             const float* __restrict__ b_off, const float* __restrict__ b_attn)
{
    const int nVal = NLAYERS_*E_*E_;
    const int nFf  = NLAYERS_*E_*DF_;
    const int nQa  = NLAYERS_*E_*512;
    int i = blockIdx.x * blockDim.x + threadIdx.x;
    if (i < nVal) { g_Wval[i] = tf32_round(W_val[i]); return; }
    i -= nVal;
    if (i < nVal) { g_Wout[i] = tf32_round(W_out[i]); return; }
    i -= nVal;
    if (i < nFf)  { g_Wff1[i] = tf32_round(W_ff1[i]); return; }
    i -= nFf;
    if (i < nFf)  { g_Wff2[i] = tf32_round(W_ff2[i]); return; }
    i -= nFf;
    if (i < nQa) {
        int l = i / (E_ * 512);
        int rem = i - l * E_ * 512;
        int k = rem >> 9;
        int c = rem & 511;
        float v = (c < 384) ? W_off[(size_t)l*E_*384 + k*384 + c]
                            : W_attn[(size_t)l*E_*128 + k*128 + (c - 384)];
        g_Wqa[i] = tf32_round(v);
        return;
    }
    i -= nQa;
    if (i < NLAYERS_ * 512) {
        int l = i >> 9;
        int c = i & 511;
        g_bqa[i] = (c < 384) ? b_off[l*384 + c] : b_attn[l*128 + (c - 384)];
    }
}
#define PREP_TOT (2*NLAYERS_*E_*E_ + 2*NLAYERS_*E_*DF_ + NLAYERS_*E_*512 + NLAYERS_*512)

// ---------------- coalesced transposing init (per level) ----------------
__global__ void init_t_kernel(const float* __restrict__ f, const float* __restrict__ p,
                              const float* __restrict__ le_row, int n, int s0)
{
    __shared__ float tf[32][33];
    __shared__ float tp[32][33];
    int i0 = blockIdx.x * 32;
    int e0 = blockIdx.y * 32;
    int b  = blockIdx.z;
    int tx = threadIdx.x, ty = threadIdx.y;

    int ig = i0 + tx;
    int eg = e0 + ty;
    if (ig < n) {
        size_t src = (size_t)(b*E_ + eg) * n + ig;
        tf[ty][tx] = f[src];
        tp[ty][tx] = p[src];
    }
    __syncthreads();

    int iw = i0 + ty;
    int ew = e0 + tx;
    if (iw < n) {
        size_t dst = (size_t)(b*S_ + s0 + iw) * E_ + ew;
        float xv = tf[tx][ty];
        float pv = tp[tx][ty] + le_row[ew];
        g_x[dst]   = xv;
        g_xr[dst]  = tf32_round(xv);
        g_pos[dst] = pv;
        g_q[dst]   = tf32_round(xv + pv);
    }
}

// ---------------- tf32 tensor-core GEMM, 3-stage cp.async, ldmatrix A ------
// mode: 0 = fp32 out, 1 = relu + tf32-round fp32 out (ff1), 2 = fp16 out (val)
template<int BMt, int BNt>
__global__ void __launch_bounds__(256, (BMt==64 ? 4 : 2))
mma_gemm(const float* __restrict__ A, const float* __restrict__ W,
         const float* __restrict__ bias, float* __restrict__ C,
         int M, int N, int K, int mode)
{
    constexpr int MI   = BMt/32;
    constexpr int NI   = BNt/32;
    constexpr int ACH  = BMt/32;
    constexpr int BCH  = BNt/32;
    constexpr int CPR  = BNt/4;
    constexpr int ASTR = 36;
    constexpr int BSTR = BNt + 8;
    constexpr int A_FL = BMt*ASTR;
    constexpr int B_FL = 32*BSTR;
    constexpr int STG  = A_FL + B_FL;

    extern __shared__ float smp[];

    int tid  = threadIdx.x;
    int lane = tid & 31;
    int wid  = tid >> 5;
    int bm = blockIdx.y * BMt;
    int bn = blockIdx.x * BNt;
    int wm = (wid >> 2) * (BMt/2);
    int wn = (wid & 3) * (BNt/4);
    int q = lane >> 2;
    int r = lane & 3;

    float acc[MI][NI][4];
    #pragma unroll
    for (int mi = 0; mi < MI; mi++)
        #pragma unroll
        for (int ni = 0; ni < NI; ni++)
            #pragma unroll
            for (int j = 0; j < 4; j++) acc[mi][ni][j] = 0.f;

    int arow[ACH], ac[ACH]; bool aval[ACH];
    #pragma unroll
    for (int i = 0; i < ACH; i++) {
        int idx = tid + i*256; arow[i] = idx >> 3; ac[i] = idx & 7;
        aval[i] = (bm + arow[i]) < M;
    }
    int brow[BCH], bc[BCH];
    #pragma unroll
    for (int i = 0; i < BCH; i++) { int idx = tid + i*256; brow[i] = idx / CPR; bc[i] = idx % CPR; }

    int nkt = K / 32;

    int mt = lane >> 3;
    int rbase = (mt & 1)*8 + (lane & 7);
    int koff = (mt >> 1)*4;
    unsigned smem_u32 = (unsigned)__cvta_generic_to_shared(smp);

    {
        float* As = smp;
        float* Bs = smp + A_FL;
        #pragma unroll
        for (int i = 0; i < ACH; i++)
            cp_async16(As + arow[i]*ASTR + ac[i]*4,
                       A + (size_t)(aval[i] ? (bm + arow[i]) : 0) * K + ac[i]*4, aval[i]);
        #pragma unroll
        for (int i = 0; i < BCH; i++)
            cp_async16(Bs + brow[i]*BSTR + bc[i]*4,
                       W + (size_t)brow[i] * N + bn + bc[i]*4, true);
        cp_commit();
        if (nkt > 1) {
            float* As1 = smp + STG;
            float* Bs1 = As1 + A_FL;
            #pragma unroll
            for (int i = 0; i < ACH; i++)
                cp_async16(As1 + arow[i]*ASTR + ac[i]*4,
                           A + (size_t)(aval[i] ? (bm + arow[i]) : 0) * K + 32 + ac[i]*4, aval[i]);
            #pragma unroll
            for (int i = 0; i < BCH; i++)
                cp_async16(Bs1 + brow[i]*BSTR + bc[i]*4,
                           W + (size_t)(32 + brow[i]) * N + bn + bc[i]*4, true);
        }
        cp_commit();
    }

    for (int kt = 0; kt < nkt; kt++) {
        int st = kt % 3;
        if (kt + 2 < nkt) {
            int s2 = (kt + 2) % 3;
            float* As = smp + s2*STG;
            float* Bs = As + A_FL;
            int kg = (kt + 2) * 32;
            #pragma unroll
            for (int i = 0; i < ACH; i++)
                cp_async16(As + arow[i]*ASTR + ac[i]*4,
                           A + (size_t)(aval[i] ? (bm + arow[i]) : 0) * K + kg + ac[i]*4, aval[i]);
            #pragma unroll
            for (int i = 0; i < BCH; i++)
                cp_async16(Bs + brow[i]*BSTR + bc[i]*4,
                           W + (size_t)(kg + brow[i]) * N + bn + bc[i]*4, true);
        }
        cp_commit();
        cp_wait<2>();
        __syncthreads();

        const float* Bs = smp + st*STG + A_FL;
        unsigned abase = smem_u32 + (unsigned)(st*STG)*4u
                       + (unsigned)((wm + rbase)*ASTR + koff)*4u;

        #pragma unroll
        for (int ks = 0; ks < 4; ks++) {
            unsigned af[MI][4], bf[NI][2];
            #pragma unroll
            for (int mi = 0; mi < MI; mi++) {
                LDSM_X4(af[mi][0], af[mi][1], af[mi][2], af[mi][3],
                        abase + (unsigned)((mi*16*ASTR + ks*8)*4));
            }
            #pragma unroll
            for (int ni = 0; ni < NI; ni++) {
                bf[ni][0] = __float_as_uint(Bs[(ks*8 + r    )*BSTR + wn + ni*8 + q]);
                bf[ni][1] = __float_as_uint(Bs[(ks*8 + r + 4)*BSTR + wn + ni*8 + q]);
            }
            #pragma unroll
            for (int mi = 0; mi < MI; mi++)
                #pragma unroll
                for (int ni = 0; ni < NI; ni++)
                    mma_tf32(acc[mi][ni], af[mi], bf[ni]);
        }
        __syncthreads();
    }

    #pragma unroll
    for (int mi = 0; mi < MI; mi++) {
        #pragma unroll
        for (int ni = 0; ni < NI; ni++) {
            int row = bm + wm + mi*16 + q;
            int col = bn + wn + ni*8 + r*2;
            float bx = bias[col], by = bias[col+1];
            float v0 = acc[mi][ni][0] + bx;
            float v1 = acc[mi][ni][1] + by;
            float v2 = acc[mi][ni][2] + bx;
            float v3 = acc[mi][ni][3] + by;
            if (mode == 1) {
                v0 = tf32_round(fmaxf(v0, 0.f)); v1 = tf32_round(fmaxf(v1, 0.f));
                v2 = tf32_round(fmaxf(v2, 0.f)); v3 = tf32_round(fmaxf(v3, 0.f));
            }
            if (mode == 2) {
                __half* Ch = (__half*)C;
                if (row < M)
                    *(__half2*)&Ch[(size_t)row * N + col] = __floats2half2_rn(v0, v1);
                if (row + 8 < M)
                    *(__half2*)&Ch[(size_t)(row + 8) * N + col] = __floats2half2_rn(v2, v3);
            } else {
                if (row < M)
                    *(float2*)&C[(size_t)row * N + col] = make_float2(v0, v1);
                if (row + 8 < M)
                    *(float2*)&C[(size_t)(row + 8) * N + col] = make_float2(v2, v3);
            }
        }
    }
}

// ---------------- deformable sampling, fp16 value, half4 loads ----------------
__global__ void sample_kernel()
{
    int warpIdx = (blockIdx.x * blockDim.x + threadIdx.x) >> 5;
    int lane  = threadIdx.x & 31;
    if (warpIdx >= M_ * NH_) return;
    int h  = warpIdx / M_;
    int bs = warpIdx - h * M_;
    int b  = bs / S_;
    int s  = bs % S_;
    int eg = lane & 7;
    int pg = lane >> 3;

    int lvl_q, iq;
    if (s < 9216)       { lvl_q = 0; iq = s;         }
    else if (s < 10368) { lvl_q = 1; iq = s - 9216;  }
    else if (s < 10512) { lvl_q = 2; iq = s - 10368; }
    else                { lvl_q = 3; iq = s - 10512; }
    int Wq = c_LW[lvl_q], Hq = c_LH[lvl_q], Dq = c_LD[lvl_q];
    int xq = iq % Wq;
    int t  = iq / Wq;
    int yq = t % Hq;
    int zq = t / Hq;
    float rx = (xq + 0.5f) / (float)Wq;
    float ry = (yq + 0.5f) / (float)Hq;
    float rz = (zq + 0.5f) / (float)Dq;

    const float4* lg4 = (const float4*)(g_oa + (size_t)bs * 512 + 384 + h * 16);
    float lv[16];
    {
        float4 v0 = lg4[0], v1 = lg4[1], v2 = lg4[2], v3 = lg4[3];
        lv[0]=v0.x; lv[1]=v0.y; lv[2]=v0.z; lv[3]=v0.w;
        lv[4]=v1.x; lv[5]=v1.y; lv[6]=v1.z; lv[7]=v1.w;
        lv[8]=v2.x; lv[9]=v2.y; lv[10]=v2.z; lv[11]=v2.w;
        lv[12]=v3.x; lv[13]=v3.y; lv[14]=v3.z; lv[15]=v3.w;
    }
    float mx = -1e30f;
    #pragma unroll
    for (int j = 0; j < 16; j++) mx = fmaxf(mx, lv[j]);
    float ssum = 0.f;
    #pragma unroll
    for (int j = 0; j < 16; j++) { lv[j] = __expf(lv[j] - mx); ssum += lv[j]; }
    float inv = 1.f / ssum;

    const float* offp = g_oa + (size_t)bs * 512 + h * (NL_*NP_*3);

    const int LDc[4]  = {4, 2, 1, 1};
    const int LHc[4]  = {48, 24, 12, 6};
    const int LWc[4]  = {48, 24, 12, 6};
    const int LS0c[4] = {0, 9216, 10368, 10512};

    float4 acc = make_float4(0.f, 0.f, 0.f, 0.f);

    #pragma unroll
    for (int lvl = 0; lvl < 4; lvl++) {
        const int Dl = LDc[lvl], Hl = LHc[lvl], Wl = LWc[lvl];
        const __half* vb = g_valh + ((size_t)b * S_ + LS0c[lvl]) * E_ + h * HD_ + eg * 4;

        float aw = lv[lvl*4 + pg] * inv;
        float ox = offp[lvl*12 + pg*3 + 0];
        float oy = offp[lvl*12 + pg*3 + 1];
        float oz = offp[lvl*12 + pg*3 + 2];
        float cx = rx * (float)Wl + ox - 0.5f;
        float cy = ry * (float)Hl + oy - 0.5f;
        float cz = rz * (float)Dl + oz - 0.5f;
        float xf = floorf(cx), yf = floorf(cy), zf = floorf(cz);
        float fx = cx - xf, fy = cy - yf, fz = cz - zf;
        int x0 = (int)xf, y0 = (int)yf, z0 = (int)zf;

        #pragma unroll
        for (int dz = 0; dz < 2; dz++) {
            int iz = z0 + dz;
            float wz = dz ? fz : 1.f - fz;
            bool vz = (iz >= 0) & (iz < Dl);
            int cz_i = min(max(iz, 0), Dl - 1);
            #pragma unroll
            for (int dy = 0; dy < 2; dy++) {
                int iy = y0 + dy;
                float wy = dy ? fy : 1.f - fy;
                bool vy = (iy >= 0) & (iy < Hl);
                int cy_i = min(max(iy, 0), Hl - 1);
                #pragma unroll
                for (int dx = 0; dx < 2; dx++) {
                    int ix = x0 + dx;
                    float wx = dx ? fx : 1.f - fx;
                    bool vx = (ix >= 0) & (ix < Wl);
                    int cx_i = min(max(ix, 0), Wl - 1);
                    float wgt = (vz & vy & vx) ? (aw * wx * wy * wz) : 0.f;
                    int idx = (cz_i*Hl + cy_i)*Wl + cx_i;
                    uint2 raw = *(const uint2*)(vb + (size_t)idx * E_);
                    __half2 h0 = *reinterpret_cast<const __half2*>(&raw.x);
                    __half2 h1 = *reinterpret_cast<const __half2*>(&raw.y);
                    float2 f0 = __half22float2(h0);
                    float2 f1 = __half22float2(h1);
                    acc.x += wgt * f0.x;
                    acc.y += wgt * f0.y;
                    acc.z += wgt * f1.x;
                    acc.w += wgt * f1.y;
                }
            }
        }
    }

    #pragma unroll
    for (int o = 8; o <= 16; o <<= 1) {
        acc.x += __shfl_xor_sync(0xFFFFFFFFu, acc.x, o);
        acc.y += __shfl_xor_sync(0xFFFFFFFFu, acc.y, o);
        acc.z += __shfl_xor_sync(0xFFFFFFFFu, acc.z, o);
        acc.w += __shfl_xor_sync(0xFFFFFFFFu, acc.w, o);
    }

    if (lane < 8) {
        float4 o4;
        o4.x = tf32_round(acc.x);
        o4.y = tf32_round(acc.y);
        o4.z = tf32_round(acc.z);
        o4.w = tf32_round(acc.w);
        *(float4*)(g_sam + (size_t)bs * E_ + h * HD_ + lane * 4) = o4;
    }
}

// ---------------- fused residual + LayerNorm: warp-per-row, 8 rows/block ----
__global__ void __launch_bounds__(256)
ln8_kernel(const float* __restrict__ x, const float* __restrict__ r,
           const float* __restrict__ g, const float* __restrict__ be,
           float* __restrict__ out, float* __restrict__ outr,
           const float* __restrict__ pos, float* __restrict__ qout)
{
    int wid  = threadIdx.x >> 5;
    int lane = threadIdx.x & 31;
    int row  = blockIdx.x * 8 + wid;   // M_ = 21096 = 2637 * 8
    size_t base = (size_t)row * E_;
    int c0 = lane * 4;
    int c1 = 128 + lane * 4;

    float4 xa = *(const float4*)(x + base + c0);
    float4 xb = *(const float4*)(x + base + c1);
    float4 ra = *(const float4*)(r + base + c0);
    float4 rb = *(const float4*)(r + base + c1);
    float4 va = make_float4(xa.x+ra.x, xa.y+ra.y, xa.z+ra.z, xa.w+ra.w);
    float4 vb = make_float4(xb.x+rb.x, xb.y+rb.y, xb.z+rb.z, xb.w+rb.w);

    float ssum = va.x+va.y+va.z+va.w + vb.x+vb.y+vb.z+vb.w;
    #pragma unroll
    for (int o = 16; o > 0; o >>= 1) ssum += __shfl_xor_sync(0xFFFFFFFFu, ssum, o);
    float mean = ssum * (1.f / E_);

    float4 da = make_float4(va.x-mean, va.y-mean, va.z-mean, va.w-mean);
    float4 db = make_float4(vb.x-mean, vb.y-mean, vb.z-mean, vb.w-mean);
    float vsum = da.x*da.x+da.y*da.y+da.z*da.z+da.w*da.w
               + db.x*db.x+db.y*db.y+db.z*db.z+db.w*db.w;
    #pragma unroll
    for (int o = 16; o > 0; o >>= 1) vsum += __shfl_xor_sync(0xFFFFFFFFu, vsum, o);
    float inv = rsqrtf(vsum * (1.f / E_) + 1e-5f);

    float4 ga = *(const float4*)(g + c0);
    float4 gb = *(const float4*)(g + c1);
    float4 ba = *(const float4*)(be + c0);
    float4 bb = *(const float4*)(be + c1);

    float4 ya = make_float4(da.x*inv*ga.x + ba.x, da.y*inv*ga.y + ba.y,
                            da.z*inv*ga.z + ba.z, da.w*inv*ga.w + ba.w);
    float4 yb = make_float4(db.x*inv*gb.x + bb.x, db.y*inv*gb.y + bb.y,
                            db.z*inv*gb.z + bb.z, db.w*inv*gb.w + bb.w);

    *(float4*)(out + base + c0) = ya;
    *(float4*)(out + base + c1) = yb;

    if (outr) {
        float4 wa = make_float4(tf32_round(ya.x), tf32_round(ya.y),
                                tf32_round(ya.z), tf32_round(ya.w));
        float4 wb = make_float4(tf32_round(yb.x), tf32_round(yb.y),
                                tf32_round(yb.z), tf32_round(yb.w));
        *(float4*)(outr + base + c0) = wa;
        *(float4*)(outr + base + c1) = wb;
    }
    if (qout) {
        float4 pa = *(const float4*)(pos + base + c0);
        float4 pb = *(const float4*)(pos + base + c1);
        float4 qa = make_float4(tf32_round(ya.x + pa.x), tf32_round(ya.y + pa.y),
                                tf32_round(ya.z + pa.z), tf32_round(ya.w + pa.w));
        float4 qb = make_float4(tf32_round(yb.x + pb.x), tf32_round(yb.y + pb.y),
                                tf32_round(yb.z + pb.z), tf32_round(yb.w + pb.w));
        *(float4*)(qout + base + c0) = qa;
        *(float4*)(qout + base + c1) = qb;
    }
}

// ---------------- host launcher ----------------
#define SMEM128 (3*(128*36 + 32*136)*4)
#define SMEM64  (3*(64*36 + 32*72)*4)

extern "C" void kernel_launch(void* const* d_in, const int* in_sizes, int n_in,
                              void* d_out, int out_size)
{
    (void)in_sizes; (void)n_in; (void)out_size;
    const float* f0 = (const float*)d_in[0];
    const float* p0 = (const float*)d_in[1];
    const float* f1 = (const float*)d_in[2];
    const float* p1 = (const float*)d_in[3];
    const float* f2 = (const float*)d_in[4];
    const float* p2 = (const float*)d_in[5];
    const float* f3 = (const float*)d_in[6];
    const float* p3 = (const float*)d_in[7];
    const float* le = (const float*)d_in[8];
    const float* W_off  = (const float*)d_in[9];
    const float* b_off  = (const float*)d_in[10];
    const float* W_attn = (const float*)d_in[11];
    const float* b_attn = (const float*)d_in[12];
    const float* W_val  = (const float*)d_in[13];
    const float* b_val  = (const float*)d_in[14];
    const float* W_out  = (const float*)d_in[15];
    const float* b_out  = (const float*)d_in[16];
    const float* ln1_g  = (const float*)d_in[17];
    const float* ln1_b  = (const float*)d_in[18];
    const float* W_ff1  = (const float*)d_in[19];
    const float* b_ff1  = (const float*)d_in[20];
    const float* W_ff2  = (const float*)d_in[21];
    const float* b_ff2  = (const float*)d_in[22];
    const float* ln2_g  = (const float*)d_in[23];
    const float* ln2_b  = (const float*)d_in[24];

    float *px, *pxr, *ppos, *pq, *psam, *ptmp, *phid, *poa;
    float *pWval, *pWqa, *pWout, *pWff1, *pWff2, *pbqa;
    void  *pvalh;
    cudaGetSymbolAddress((void**)&px,    g_x);
    cudaGetSymbolAddress((void**)&pxr,   g_xr);
    cudaGetSymbolAddress((void**)&ppos,  g_pos);
    cudaGetSymbolAddress((void**)&pq,    g_q);
    cudaGetSymbolAddress(&pvalh,         g_valh);
    cudaGetSymbolAddress((void**)&psam,  g_sam);
    cudaGetSymbolAddress((void**)&ptmp,  g_tmp);
    cudaGetSymbolAddress((void**)&phid,  g_hid);
    cudaGetSymbolAddress((void**)&poa,   g_oa);
    cudaGetSymbolAddress((void**)&pWval, g_Wval);
    cudaGetSymbolAddress((void**)&pWqa,  g_Wqa);
    cudaGetSymbolAddress((void**)&pWout, g_Wout);
    cudaGetSymbolAddress((void**)&pWff1, g_Wff1);
    cudaGetSymbolAddress((void**)&pWff2, g_Wff2);
    cudaGetSymbolAddress((void**)&pbqa,  g_bqa);

    cudaFuncSetAttribute(mma_gemm<128,128>, cudaFuncAttributeMaxDynamicSharedMemorySize, SMEM128);
    cudaFuncSetAttribute(mma_gemm<64,64>,   cudaFuncAttributeMaxDynamicSharedMemorySize, SMEM64);

    // launch 1: merged weight prep
    prep_weights<<<(PREP_TOT + 255)/256, 256>>>(W_val, W_out, W_ff1, W_ff2,
                                                W_off, W_attn, b_off, b_attn);

    // launches 2-5: transposing init, one per level
    {
        dim3 blk(32, 32);
        init_t_kernel<<<dim3(288, 8, B_), blk>>>(f0, p0, le + 0*E_, 9216, 0);
        init_t_kernel<<<dim3( 36, 8, B_), blk>>>(f1, p1, le + 1*E_, 1152, 9216);
        init_t_kernel<<<dim3(  5, 8, B_), blk>>>(f2, p2, le + 2*E_,  144, 10368);
        init_t_kernel<<<dim3(  2, 8, B_), blk>>>(f3, p3, le + 3*E_,   36, 10512);
    }

    const int GM64  = (M_ + 63) / 64;    // 330
    const int GM128 = (M_ + 127) / 128;  // 165
    const int LNB   = M_ / 8;            // 2637

    for (int l = 0; l < NLAYERS_; l++) {
        // value proj -> fp16 output (mode 2)
        mma_gemm<64,64><<<dim3(E_/64, GM64), 256, SMEM64>>>(pxr, pWval + (size_t)l*E_*E_,
                                           b_val + l*E_, (float*)pvalh, M_, E_, E_, 2);
        mma_gemm<128,128><<<dim3(512/128, GM128), 256, SMEM128>>>(pq, pWqa + (size_t)l*E_*512,
                                            pbqa + l*512, poa, M_, 512, E_, 0);

        sample_kernel<<<(M_ * NH_ * 32) / 256, 256>>>();

        mma_gemm<64,64><<<dim3(E_/64, GM64), 256, SMEM64>>>(psam, pWout + (size_t)l*E_*E_,
                                           b_out + l*E_, ptmp, M_, E_, E_, 0);
        ln8_kernel<<<LNB, 256>>>(px, ptmp, ln1_g + l*E_, ln1_b + l*E_, px, pxr,
                                 (const float*)0, (float*)0);

        mma_gemm<128,128><<<dim3(DF_/128, GM128), 256, SMEM128>>>(pxr, pWff1 + (size_t)l*E_*DF_,
                                            b_ff1 + l*DF_, phid, M_, DF_, E_, 1);
        mma_gemm<64,64><<<dim3(E_/64, GM64), 256, SMEM64>>>(phid, pWff2 + (size_t)l*DF_*E_,
                                           b_ff2 + l*E_, ptmp, M_, E_, DF_, 0);

        if (l == NLAYERS_ - 1) {
            ln8_kernel<<<LNB, 256>>>(px, ptmp, ln2_g + l*E_, ln2_b + l*E_,
                                     (float*)d_out, (float*)0, (const float*)0, (float*)0);
        } else {
            ln8_kernel<<<LNB, 256>>>(px, ptmp, ln2_g + l*E_, ln2_b + l*E_,
                                     px, pxr, ppos, pq);
        }
    }
}

// round 13
// speedup vs baseline: 1.3159x; 1.2778x over previous
#include <cuda_runtime.h>
#include <cuda_fp16.h>
#include <math.h>
#include <stdint.h>

// ---------------- problem constants ----------------
#define B_ 2
#define E_ 256
#define NH_ 8
#define NL_ 4
#define NP_ 4
#define DF_ 1024
#define NLAYERS_ 6
#define HD_ 32
#define S_ 10548
#define M_ (B_*S_)          // 21096 query rows

__device__ __constant__ int c_LD[4] = {4, 2, 1, 1};
__device__ __constant__ int c_LH[4] = {48, 24, 12, 6};
__device__ __constant__ int c_LW[4] = {48, 24, 12, 6};

// ---------------- scratch (allocation-free) ----------------
__device__ float  g_x   [M_*E_];    // fp32 residual stream
__device__ __half g_xh  [M_*E_];    // fp16 copy of x (GEMM A)
__device__ float  g_pos [M_*E_];
__device__ __half g_qh  [M_*E_];    // fp16 q = x + pos (GEMM A)
__device__ __half g_valh[M_*E_];    // fp16 value tensor
__device__ __half g_samh[M_*E_];    // fp16 sampler output (GEMM A)
__device__ float  g_tmp [M_*E_];
__device__ float  g_oa  [M_*512];   // packed: [0,384) offsets, [384,512) attn logits
__device__ __half g_hidh[M_*DF_];   // fp16 hidden (GEMM A)

// fp16 weights [K,N] row-major
__device__ __half g_Wval[NLAYERS_*E_*E_];
__device__ __half g_Wqa [NLAYERS_*E_*512];
__device__ __half g_Wout[NLAYERS_*E_*E_];
__device__ __half g_Wff1[NLAYERS_*E_*DF_];
__device__ __half g_Wff2[NLAYERS_*DF_*E_];
__device__ float  g_bqa [NLAYERS_*512];

// ---------------- helpers ----------------
__device__ __forceinline__ void mma_f16(float c[4], const unsigned a[4], const unsigned b[2])
{
    asm volatile("mma.sync.aligned.m16n8k16.row.col.f32.f16.f16.f32 "
        "{%0,%1,%2,%3}, {%4,%5,%6,%7}, {%8,%9}, {%0,%1,%2,%3};\n"
        : "+f"(c[0]), "+f"(c[1]), "+f"(c[2]), "+f"(c[3])
        : "r"(a[0]), "r"(a[1]), "r"(a[2]), "r"(a[3]), "r"(b[0]), "r"(b[1]));
}

__device__ __forceinline__ void cp_async16(void* smem, const void* gmem, bool valid)
{
    unsigned saddr = (unsigned)__cvta_generic_to_shared(smem);
    int sz = valid ? 16 : 0;
    asm volatile("cp.async.cg.shared.global [%0], [%1], 16, %2;\n"
                 :: "r"(saddr), "l"(gmem), "r"(sz));
}
__device__ __forceinline__ void cp_commit() { asm volatile("cp.async.commit_group;\n"); }
template<int N> __device__ __forceinline__ void cp_wait() { asm volatile("cp.async.wait_group %0;\n" :: "n"(N)); }

#define LDSM_X4(r0,r1,r2,r3,addr) \
    asm volatile("ldmatrix.sync.aligned.m8n8.x4.shared.b16 {%0,%1,%2,%3}, [%4];\n" \
        : "=r"(r0), "=r"(r1), "=r"(r2), "=r"(r3) : "r"(addr))

#define LDSM_X4T(r0,r1,r2,r3,addr) \
    asm volatile("ldmatrix.sync.aligned.m8n8.x4.trans.shared.b16 {%0,%1,%2,%3}, [%4];\n" \
        : "=r"(r0), "=r"(r1), "=r"(r2), "=r"(r3) : "r"(addr))

__device__ __forceinline__ void store_half4(__half* p, float a, float b, float c, float d)
{
    __half2 h01 = __floats2half2_rn(a, b);
    __half2 h23 = __floats2half2_rn(c, d);
    uint2 u;
    u.x = *reinterpret_cast<unsigned*>(&h01);
    u.y = *reinterpret_cast<unsigned*>(&h23);
    *reinterpret_cast<uint2*>(p) = u;
}

// ---------------- merged weight prep (single launch) ----------------
__global__ void prep_weights(const float* __restrict__ W_val, const float* __restrict__ W_out,
                             const float* __restrict__ W_ff1, const float* __restrict__ W_ff2,
                             const float* __restrict__ W_off, const float* __restrict__ W_attn,
                             const float* __restrict__ b_off, const float* __restrict__ b_attn)
{
    const int nVal = NLAYERS_*E_*E_;
    const int nFf  = NLAYERS_*E_*DF_;
    const int nQa  = NLAYERS_*E_*512;
    int i = blockIdx.x * blockDim.x + threadIdx.x;
    if (i < nVal) { g_Wval[i] = __float2half_rn(W_val[i]); return; }
    i -= nVal;
    if (i < nVal) { g_Wout[i] = __float2half_rn(W_out[i]); return; }
    i -= nVal;
    if (i < nFf)  { g_Wff1[i] = __float2half_rn(W_ff1[i]); return; }
    i -= nFf;
    if (i < nFf)  { g_Wff2[i] = __float2half_rn(W_ff2[i]); return; }
    i -= nFf;
    if (i < nQa) {
        int l = i / (E_ * 512);
        int rem = i - l * E_ * 512;
        int k = rem >> 9;
        int c = rem & 511;
        float v = (c < 384) ? W_off[(size_t)l*E_*384 + k*384 + c]
                            : W_attn[(size_t)l*E_*128 + k*128 + (c - 384)];
        g_Wqa[i] = __float2half_rn(v);
        return;
    }
    i -= nQa;
    if (i < NLAYERS_ * 512) {
        int l = i >> 9;
        int c = i & 511;
        g_bqa[i] = (c < 384) ? b_off[l*384 + c] : b_attn[l*128 + (c - 384)];
    }
}
#define PREP_TOT (2*NLAYERS_*E_*E_ + 2*NLAYERS_*E_*DF_ + NLAYERS_*E_*512 + NLAYERS_*512)

// ---------------- coalesced transposing init (per level) ----------------
__global__ void init_t_kernel(const float* __restrict__ f, const float* __restrict__ p,
                              const float* __restrict__ le_row, int n, int s0)
{
    __shared__ float tf[32][33];
    __shared__ float tp[32][33];
    int i0 = blockIdx.x * 32;
    int e0 = blockIdx.y * 32;
    int b  = blockIdx.z;
    int tx = threadIdx.x, ty = threadIdx.y;

    int ig = i0 + tx;
    int eg = e0 + ty;
    if (ig < n) {
        size_t src = (size_t)(b*E_ + eg) * n + ig;
        tf[ty][tx] = f[src];
        tp[ty][tx] = p[src];
    }
    __syncthreads();

    int iw = i0 + ty;
    int ew = e0 + tx;
    if (iw < n) {
        size_t dst = (size_t)(b*S_ + s0 + iw) * E_ + ew;
        float xv = tf[tx][ty];
        float pv = tp[tx][ty] + le_row[ew];
        g_x[dst]   = xv;
        g_xh[dst]  = __float2half_rn(xv);
        g_pos[dst] = pv;
        g_qh[dst]  = __float2half_rn(xv + pv);
    }
}

// ---------------- fp16 tensor-core GEMM (m16n8k16), 3-stage cp.async ------
// C = A[M,K](fp16) @ W[K,N](fp16) + bias(fp32)
// mode: 0 = fp32 out, 1 = relu + fp16 out, 2 = fp16 out
template<int BMt, int BNt>
__global__ void __launch_bounds__(256, (BMt==64 ? 4 : 2))
mma_gemm(const __half* __restrict__ A, const __half* __restrict__ W,
         const float* __restrict__ bias, void* __restrict__ Cv,
         int M, int N, int K, int mode)
{
    constexpr int MI   = BMt/32;         // m16 tiles per warp (warp m = BMt/2)
    constexpr int NI   = BNt/32;         // n8 tiles per warp (warp n = BNt/4)
    constexpr int ACH  = BMt/64;         // A 16B chunks per thread (BM*4/256)
    constexpr int BCH  = BNt/64;         // B 16B chunks per thread (32*(BN/8)/256)
    constexpr int BCPR = BNt/8;          // B chunks per k-row
    constexpr int ASTR = 40;             // halves per A row (80B = 20 banks, conflict-free)
    constexpr int BSTR = BNt + 8;        // halves per B row
    constexpr int A_FL = BMt*ASTR;       // halves
    constexpr int B_FL = 32*BSTR;        // halves
    constexpr int STG  = A_FL + B_FL;    // halves per stage

    extern __shared__ __half smh[];

    int tid  = threadIdx.x;
    int lane = tid & 31;
    int wid  = tid >> 5;
    int bm = blockIdx.y * BMt;
    int bn = blockIdx.x * BNt;
    int wm = (wid >> 2) * (BMt/2);
    int wn = (wid & 3) * (BNt/4);
    int q = lane >> 2;
    int r = lane & 3;

    float acc[MI][NI][4];
    #pragma unroll
    for (int mi = 0; mi < MI; mi++)
        #pragma unroll
        for (int ni = 0; ni < NI; ni++)
            #pragma unroll
            for (int j = 0; j < 4; j++) acc[mi][ni][j] = 0.f;

    // cp.async maps: A rows of 32 halves = 4 chunks; B rows of BNt halves = BNt/8 chunks
    int arow[ACH], ac8[ACH]; bool aval[ACH];
    #pragma unroll
    for (int i = 0; i < ACH; i++) {
        int idx = tid + i*256; arow[i] = idx >> 2; ac8[i] = idx & 3;
        aval[i] = (bm + arow[i]) < M;
    }
    int brow[BCH], bc8[BCH];
    #pragma unroll
    for (int i = 0; i < BCH; i++) { int idx = tid + i*256; brow[i] = idx / BCPR; bc8[i] = idx % BCPR; }

    int nkt = K / 32;

    unsigned smem_u32 = (unsigned)__cvta_generic_to_shared(smh);
    // ldmatrix lane constants
    //  A (x4, non-trans): lane&15 = row in 16-row tile, lane>>4 = k-half (+8 halves)
    unsigned a_lane_off = (unsigned)(((lane & 15) * ASTR + (lane >> 4) * 8) * 2);
    //  B (x4, trans): row = ((lane>>3)&1)*8 + (lane&7); col = (lane>>4)*8
    unsigned b_lane_off = (unsigned)(((((lane >> 3) & 1) * 8 + (lane & 7)) * BSTR
                                      + (lane >> 4) * 8) * 2);

    auto load_stage = [&](int slot, int kg) {
        __half* As = smh + slot*STG;
        __half* Bs = As + A_FL;
        #pragma unroll
        for (int i = 0; i < ACH; i++)
            cp_async16(As + arow[i]*ASTR + ac8[i]*8,
                       A + (size_t)(aval[i] ? (bm + arow[i]) : 0) * K + kg + ac8[i]*8, aval[i]);
        #pragma unroll
        for (int i = 0; i < BCH; i++)
            cp_async16(Bs + brow[i]*BSTR + bc8[i]*8,
                       W + (size_t)(kg + brow[i]) * N + bn + bc8[i]*8, true);
    };

    load_stage(0, 0);
    cp_commit();
    if (nkt > 1) load_stage(1, 32);
    cp_commit();

    for (int kt = 0; kt < nkt; kt++) {
        int st = kt % 3;
        if (kt + 2 < nkt) load_stage((kt + 2) % 3, (kt + 2) * 32);
        cp_commit();
        cp_wait<2>();
        __syncthreads();

        unsigned abase = smem_u32 + (unsigned)(st*STG)*2u + (unsigned)(wm*ASTR)*2u + a_lane_off;
        unsigned bbase = smem_u32 + (unsigned)((st*STG + A_FL))*2u + (unsigned)wn*2u + b_lane_off;

        #pragma unroll
        for (int ks = 0; ks < 2; ks++) {
            unsigned af[MI][4], bf[NI][2];
            #pragma unroll
            for (int mi = 0; mi < MI; mi++) {
                LDSM_X4(af[mi][0], af[mi][1], af[mi][2], af[mi][3],
                        abase + (unsigned)((mi*16*ASTR + ks*16)*2));
            }
            #pragma unroll
            for (int nb = 0; nb < NI/2; nb++) {
                LDSM_X4T(bf[2*nb][0], bf[2*nb][1], bf[2*nb+1][0], bf[2*nb+1][1],
                         bbase + (unsigned)((ks*16*BSTR + nb*16)*2));
            }
            #pragma unroll
            for (int mi = 0; mi < MI; mi++)
                #pragma unroll
                for (int ni = 0; ni < NI; ni++)
                    mma_f16(acc[mi][ni], af[mi], bf[ni]);
        }
        __syncthreads();
    }

    // epilogue (same m16n8 output layout as tf32 path)
    #pragma unroll
    for (int mi = 0; mi < MI; mi++) {
        #pragma unroll
        for (int ni = 0; ni < NI; ni++) {
            int row = bm + wm + mi*16 + q;
            int col = bn + wn + ni*8 + r*2;
            float bx = bias[col], by = bias[col+1];
            float v0 = acc[mi][ni][0] + bx;
            float v1 = acc[mi][ni][1] + by;
            float v2 = acc[mi][ni][2] + bx;
            float v3 = acc[mi][ni][3] + by;
            if (mode == 1) {
                v0 = fmaxf(v0, 0.f); v1 = fmaxf(v1, 0.f);
                v2 = fmaxf(v2, 0.f); v3 = fmaxf(v3, 0.f);
            }
            if (mode == 0) {
                float* C = (float*)Cv;
                if (row < M)
                    *(float2*)&C[(size_t)row * N + col] = make_float2(v0, v1);
                if (row + 8 < M)
                    *(float2*)&C[(size_t)(row + 8) * N + col] = make_float2(v2, v3);
            } else {
                __half* Ch = (__half*)Cv;
                if (row < M)
                    *(__half2*)&Ch[(size_t)row * N + col] = __floats2half2_rn(v0, v1);
                if (row + 8 < M)
                    *(__half2*)&Ch[(size_t)(row + 8) * N + col] = __floats2half2_rn(v2, v3);
            }
        }
    }
}

// ---------------- deformable sampling, fp16 value, half4 loads ----------------
__global__ void sample_kernel()
{
    int warpIdx = (blockIdx.x * blockDim.x + threadIdx.x) >> 5;
    int lane  = threadIdx.x & 31;
    if (warpIdx >= M_ * NH_) return;
    int h  = warpIdx / M_;
    int bs = warpIdx - h * M_;
    int b  = bs / S_;
    int s  = bs % S_;
    int eg = lane & 7;
    int pg = lane >> 3;

    int lvl_q, iq;
    if (s < 9216)       { lvl_q = 0; iq = s;         }
    else if (s < 10368) { lvl_q = 1; iq = s - 9216;  }
    else if (s < 10512) { lvl_q = 2; iq = s - 10368; }
    else                { lvl_q = 3; iq = s - 10512; }
    int Wq = c_LW[lvl_q], Hq = c_LH[lvl_q], Dq = c_LD[lvl_q];
    int xq = iq % Wq;
    int t  = iq / Wq;
    int yq = t % Hq;
    int zq = t / Hq;
    float rx = (xq + 0.5f) / (float)Wq;
    float ry = (yq + 0.5f) / (float)Hq;
    float rz = (zq + 0.5f) / (float)Dq;

    const float4* lg4 = (const float4*)(g_oa + (size_t)bs * 512 + 384 + h * 16);
    float lv[16];
    {
        float4 v0 = lg4[0], v1 = lg4[1], v2 = lg4[2], v3 = lg4[3];
        lv[0]=v0.x; lv[1]=v0.y; lv[2]=v0.z; lv[3]=v0.w;
        lv[4]=v1.x; lv[5]=v1.y; lv[6]=v1.z; lv[7]=v1.w;
        lv[8]=v2.x; lv[9]=v2.y; lv[10]=v2.z; lv[11]=v2.w;
        lv[12]=v3.x; lv[13]=v3.y; lv[14]=v3.z; lv[15]=v3.w;
    }
    float mx = -1e30f;
    #pragma unroll
    for (int j = 0; j < 16; j++) mx = fmaxf(mx, lv[j]);
    float ssum = 0.f;
    #pragma unroll
    for (int j = 0; j < 16; j++) { lv[j] = __expf(lv[j] - mx); ssum += lv[j]; }
    float inv = 1.f / ssum;

    const float* offp = g_oa + (size_t)bs * 512 + h * (NL_*NP_*3);

    const int LDc[4]  = {4, 2, 1, 1};
    const int LHc[4]  = {48, 24, 12, 6};
    const int LWc[4]  = {48, 24, 12, 6};
    const int LS0c[4] = {0, 9216, 10368, 10512};

    float4 acc = make_float4(0.f, 0.f, 0.f, 0.f);

    #pragma unroll
    for (int lvl = 0; lvl < 4; lvl++) {
        const int Dl = LDc[lvl], Hl = LHc[lvl], Wl = LWc[lvl];
        const __half* vb = g_valh + ((size_t)b * S_ + LS0c[lvl]) * E_ + h * HD_ + eg * 4;

        float aw = lv[lvl*4 + pg] * inv;
        float ox = offp[lvl*12 + pg*3 + 0];
        float oy = offp[lvl*12 + pg*3 + 1];
        float oz = offp[lvl*12 + pg*3 + 2];
        float cx = rx * (float)Wl + ox - 0.5f;
        float cy = ry * (float)Hl + oy - 0.5f;
        float cz = rz * (float)Dl + oz - 0.5f;
        float xf = floorf(cx), yf = floorf(cy), zf = floorf(cz);
        float fx = cx - xf, fy = cy - yf, fz = cz - zf;
        int x0 = (int)xf, y0 = (int)yf, z0 = (int)zf;

        #pragma unroll
        for (int dz = 0; dz < 2; dz++) {
            int iz = z0 + dz;
            float wz = dz ? fz : 1.f - fz;
            bool vz = (iz >= 0) & (iz < Dl);
            int cz_i = min(max(iz, 0), Dl - 1);
            #pragma unroll
            for (int dy = 0; dy < 2; dy++) {
                int iy = y0 + dy;
                float wy = dy ? fy : 1.f - fy;
                bool vy = (iy >= 0) & (iy < Hl);
                int cy_i = min(max(iy, 0), Hl - 1);
                #pragma unroll
                for (int dx = 0; dx < 2; dx++) {
                    int ix = x0 + dx;
                    float wx = dx ? fx : 1.f - fx;
                    bool vx = (ix >= 0) & (ix < Wl);
                    int cx_i = min(max(ix, 0), Wl - 1);
                    float wgt = (vz & vy & vx) ? (aw * wx * wy * wz) : 0.f;
                    int idx = (cz_i*Hl + cy_i)*Wl + cx_i;
                    uint2 raw = *(const uint2*)(vb + (size_t)idx * E_);
                    __half2 h0 = *reinterpret_cast<const __half2*>(&raw.x);
                    __half2 h1 = *reinterpret_cast<const __half2*>(&raw.y);
                    float2 f0 = __half22float2(h0);
                    float2 f1 = __half22float2(h1);
                    acc.x += wgt * f0.x;
                    acc.y += wgt * f0.y;
                    acc.z += wgt * f1.x;
                    acc.w += wgt * f1.y;
                }
            }
        }
    }

    #pragma unroll
    for (int o = 8; o <= 16; o <<= 1) {
        acc.x += __shfl_xor_sync(0xFFFFFFFFu, acc.x, o);
        acc.y += __shfl_xor_sync(0xFFFFFFFFu, acc.y, o);
        acc.z += __shfl_xor_sync(0xFFFFFFFFu, acc.z, o);
        acc.w += __shfl_xor_sync(0xFFFFFFFFu, acc.w, o);
    }

    if (lane < 8) {
        store_half4(g_samh + (size_t)bs * E_ + h * HD_ + lane * 4,
                    acc.x, acc.y, acc.z, acc.w);
    }
}

// ---------------- fused residual + LayerNorm: warp-per-row, 8 rows/block ----
__global__ void __launch_bounds__(256)
ln8_kernel(const float* __restrict__ x, const float* __restrict__ r,
           const float* __restrict__ g, const float* __restrict__ be,
           float* __restrict__ out, __half* __restrict__ outh,
           const float* __restrict__ pos, __half* __restrict__ qouth)
{
    int wid  = threadIdx.x >> 5;
    int lane = threadIdx.x & 31;
    int row  = blockIdx.x * 8 + wid;   // M_ = 21096 = 2637 * 8
    size_t base = (size_t)row * E_;
    int c0 = lane * 4;
    int c1 = 128 + lane * 4;

    float4 xa = *(const float4*)(x + base + c0);
    float4 xb = *(const float4*)(x + base + c1);
    float4 ra = *(const float4*)(r + base + c0);
    float4 rb = *(const float4*)(r + base + c1);
    float4 va = make_float4(xa.x+ra.x, xa.y+ra.y, xa.z+ra.z, xa.w+ra.w);
    float4 vb = make_float4(xb.x+rb.x, xb.y+rb.y, xb.z+rb.z, xb.w+rb.w);

    float ssum = va.x+va.y+va.z+va.w + vb.x+vb.y+vb.z+vb.w;
    #pragma unroll
    for (int o = 16; o > 0; o >>= 1) ssum += __shfl_xor_sync(0xFFFFFFFFu, ssum, o);
    float mean = ssum * (1.f / E_);

    float4 da = make_float4(va.x-mean, va.y-mean, va.z-mean, va.w-mean);
    float4 db = make_float4(vb.x-mean, vb.y-mean, vb.z-mean, vb.w-mean);
    float vsum = da.x*da.x+da.y*da.y+da.z*da.z+da.w*da.w
               + db.x*db.x+db.y*db.y+db.z*db.z+db.w*db.w;
    #pragma unroll
    for (int o = 16; o > 0; o >>= 1) vsum += __shfl_xor_sync(0xFFFFFFFFu, vsum, o);
    float inv = rsqrtf(vsum * (1.f / E_) + 1e-5f);

    float4 ga = *(const float4*)(g + c0);
    float4 gb = *(const float4*)(g + c1);
    float4 ba = *(const float4*)(be + c0);
    float4 bb = *(const float4*)(be + c1);

    float4 ya = make_float4(da.x*inv*ga.x + ba.x, da.y*inv*ga.y + ba.y,
                            da.z*inv*ga.z + ba.z, da.w*inv*ga.w + ba.w);
    float4 yb = make_float4(db.x*inv*gb.x + bb.x, db.y*inv*gb.y + bb.y,
                            db.z*inv*gb.z + bb.z, db.w*inv*gb.w + bb.w);

    *(float4*)(out + base + c0) = ya;
    *(float4*)(out + base + c1) = yb;

    if (outh) {
        store_half4(outh + base + c0, ya.x, ya.y, ya.z, ya.w);
        store_half4(outh + base + c1, yb.x, yb.y, yb.z, yb.w);
    }
    if (qouth) {
        float4 pa = *(const float4*)(pos + base + c0);
        float4 pb = *(const float4*)(pos + base + c1);
        store_half4(qouth + base + c0, ya.x + pa.x, ya.y + pa.y, ya.z + pa.z, ya.w + pa.w);
        store_half4(qouth + base + c1, yb.x + pb.x, yb.y + pb.y, yb.z + pb.z, yb.w + pb.w);
    }
}

// ---------------- host launcher ----------------
// smem bytes = 3 * (BM*40 + 32*(BN+8)) * 2
#define SMEM128 (3*(128*40 + 32*136)*2)   // 56832
#define SMEM64  (3*(64*40 + 32*72)*2)     // 29184

extern "C" void kernel_launch(void* const* d_in, const int* in_sizes, int n_in,
                              void* d_out, int out_size)
{
    (void)in_sizes; (void)n_in; (void)out_size;
    const float* f0 = (const float*)d_in[0];
    const float* p0 = (const float*)d_in[1];
    const float* f1 = (const float*)d_in[2];
    const float* p1 = (const float*)d_in[3];
    const float* f2 = (const float*)d_in[4];
    const float* p2 = (const float*)d_in[5];
    const float* f3 = (const float*)d_in[6];
    const float* p3 = (const float*)d_in[7];
    const float* le = (const float*)d_in[8];
    const float* W_off  = (const float*)d_in[9];
    const float* b_off  = (const float*)d_in[10];
    const float* W_attn = (const float*)d_in[11];
    const float* b_attn = (const float*)d_in[12];
    const float* W_val  = (const float*)d_in[13];
    const float* b_val  = (const float*)d_in[14];
    const float* W_out  = (const float*)d_in[15];
    const float* b_out  = (const float*)d_in[16];
    const float* ln1_g  = (const float*)d_in[17];
    const float* ln1_b  = (const float*)d_in[18];
    const float* W_ff1  = (const float*)d_in[19];
    const float* b_ff1  = (const float*)d_in[20];
    const float* W_ff2  = (const float*)d_in[21];
    const float* b_ff2  = (const float*)d_in[22];
    const float* ln2_g  = (const float*)d_in[23];
    const float* ln2_b  = (const float*)d_in[24];

    float  *px, *ppos, *ptmp, *poa, *pbqa;
    __half *pxh, *pqh, *pvalh, *psamh, *phidh;
    __half *pWval, *pWqa, *pWout, *pWff1, *pWff2;
    cudaGetSymbolAddress((void**)&px,    g_x);
    cudaGetSymbolAddress((void**)&pxh,   g_xh);
    cudaGetSymbolAddress((void**)&ppos,  g_pos);
    cudaGetSymbolAddress((void**)&pqh,   g_qh);
    cudaGetSymbolAddress((void**)&pvalh, g_valh);
    cudaGetSymbolAddress((void**)&psamh, g_samh);
    cudaGetSymbolAddress((void**)&ptmp,  g_tmp);
    cudaGetSymbolAddress((void**)&phidh, g_hidh);
    cudaGetSymbolAddress((void**)&poa,   g_oa);
    cudaGetSymbolAddress((void**)&pWval, g_Wval);
    cudaGetSymbolAddress((void**)&pWqa,  g_Wqa);
    cudaGetSymbolAddress((void**)&pWout, g_Wout);
    cudaGetSymbolAddress((void**)&pWff1, g_Wff1);
    cudaGetSymbolAddress((void**)&pWff2, g_Wff2);
    cudaGetSymbolAddress((void**)&pbqa,  g_bqa);

    cudaFuncSetAttribute(mma_gemm<128,128>, cudaFuncAttributeMaxDynamicSharedMemorySize, SMEM128);
    cudaFuncSetAttribute(mma_gemm<64,64>,   cudaFuncAttributeMaxDynamicSharedMemorySize, SMEM64);

    // launch 1: merged weight prep
    prep_weights<<<(PREP_TOT + 255)/256, 256>>>(W_val, W_out, W_ff1, W_ff2,
                                                W_off, W_attn, b_off, b_attn);

    // launches 2-5: transposing init, one per level
    {
        dim3 blk(32, 32);
        init_t_kernel<<<dim3(288, 8, B_), blk>>>(f0, p0, le + 0*E_, 9216, 0);
        init_t_kernel<<<dim3( 36, 8, B_), blk>>>(f1, p1, le + 1*E_, 1152, 9216);
        init_t_kernel<<<dim3(  5, 8, B_), blk>>>(f2, p2, le + 2*E_,  144, 10368);
        init_t_kernel<<<dim3(  2, 8, B_), blk>>>(f3, p3, le + 3*E_,   36, 10512);
    }

    const int GM64  = (M_ + 63) / 64;    // 330
    const int GM128 = (M_ + 127) / 128;  // 165
    const int LNB   = M_ / 8;            // 2637

    for (int l = 0; l < NLAYERS_; l++) {
        // value proj -> fp16 out
        mma_gemm<64,64><<<dim3(E_/64, GM64), 256, SMEM64>>>(pxh, pWval + (size_t)l*E_*E_,
                                           b_val + l*E_, pvalh, M_, E_, E_, 2);
        // offsets + attn logits -> fp32 out
        mma_gemm<128,128><<<dim3(512/128, GM128), 256, SMEM128>>>(pqh, pWqa + (size_t)l*E_*512,
                                            pbqa + l*512, poa, M_, 512, E_, 0);

        sample_kernel<<<(M_ * NH_ * 32) / 256, 256>>>();

        // out proj: A = sampler fp16, fp32 out
        mma_gemm<64,64><<<dim3(E_/64, GM64), 256, SMEM64>>>(psamh, pWout + (size_t)l*E_*E_,
                                           b_out + l*E_, ptmp, M_, E_, E_, 0);
        ln8_kernel<<<LNB, 256>>>(px, ptmp, ln1_g + l*E_, ln1_b + l*E_, px, pxh,
                                 (const float*)0, (__half*)0);

        // ff1: relu + fp16 out
        mma_gemm<128,128><<<dim3(DF_/128, GM128), 256, SMEM128>>>(pxh, pWff1 + (size_t)l*E_*DF_,
                                            b_ff1 + l*DF_, phidh, M_, DF_, E_, 1);
        // ff2: A = hid fp16, fp32 out
        mma_gemm<64,64><<<dim3(E_/64, GM64), 256, SMEM64>>>(phidh, pWff2 + (size_t)l*DF_*E_,
                                           b_ff2 + l*E_, ptmp, M_, E_, DF_, 0);

        if (l == NLAYERS_ - 1) {
            ln8_kernel<<<LNB, 256>>>(px, ptmp, ln2_g + l*E_, ln2_b + l*E_,
                                     (float*)d_out, (__half*)0, (const float*)0, (__half*)0);
        } else {
            ln8_kernel<<<LNB, 256>>>(px, ptmp, ln2_g + l*E_, ln2_b + l*E_,
                                     px, pxh, ppos, pqh);
        }
    }
}

// round 14
// speedup vs baseline: 1.3672x; 1.0390x over previous
#include <cuda_runtime.h>
#include <cuda_fp16.h>
#include <math.h>
#include <stdint.h>

// ---------------- problem constants ----------------
#define B_ 2
#define E_ 256
#define NH_ 8
#define NL_ 4
#define NP_ 4
#define DF_ 1024
#define NLAYERS_ 6
#define HD_ 32
#define S_ 10548
#define M_ (B_*S_)          // 21096 query rows

__device__ __constant__ int c_LD[4] = {4, 2, 1, 1};
__device__ __constant__ int c_LH[4] = {48, 24, 12, 6};
__device__ __constant__ int c_LW[4] = {48, 24, 12, 6};

// ---------------- scratch (allocation-free) ----------------
__device__ float  g_x   [M_*E_];    // fp32 residual stream
__device__ __half g_xh  [M_*E_];    // fp16 copy of x (GEMM A)
__device__ float  g_pos [M_*E_];
__device__ __half g_qh  [M_*E_];    // fp16 q = x + pos (GEMM A)
__device__ __half g_valh[M_*E_];    // fp16 value tensor
__device__ __half g_samh[M_*E_];    // fp16 sampler output (GEMM A)
__device__ float  g_tmp [M_*E_];
__device__ float  g_oa  [M_*512];   // packed: [0,384) offsets, [384,512) attn logits
__device__ __half g_hidh[M_*DF_];   // fp16 hidden (GEMM A)

// fp16 weights [K,N] row-major
__device__ __half g_Wval[NLAYERS_*E_*E_];
__device__ __half g_Wqa [NLAYERS_*E_*512];
__device__ __half g_Wout[NLAYERS_*E_*E_];
__device__ __half g_Wff1[NLAYERS_*E_*DF_];
__device__ __half g_Wff2[NLAYERS_*DF_*E_];
__device__ float  g_bqa [NLAYERS_*512];

// ---------------- helpers ----------------
__device__ __forceinline__ void mma_f16(float c[4], const unsigned a[4], const unsigned b[2])
{
    asm volatile("mma.sync.aligned.m16n8k16.row.col.f32.f16.f16.f32 "
        "{%0,%1,%2,%3}, {%4,%5,%6,%7}, {%8,%9}, {%0,%1,%2,%3};\n"
        : "+f"(c[0]), "+f"(c[1]), "+f"(c[2]), "+f"(c[3])
        : "r"(a[0]), "r"(a[1]), "r"(a[2]), "r"(a[3]), "r"(b[0]), "r"(b[1]));
}

__device__ __forceinline__ void cp_async16(void* smem, const void* gmem, bool valid)
{
    unsigned saddr = (unsigned)__cvta_generic_to_shared(smem);
    int sz = valid ? 16 : 0;
    asm volatile("cp.async.cg.shared.global [%0], [%1], 16, %2;\n"
                 :: "r"(saddr), "l"(gmem), "r"(sz));
}
__device__ __forceinline__ void cp_commit() { asm volatile("cp.async.commit_group;\n"); }
template<int N> __device__ __forceinline__ void cp_wait() { asm volatile("cp.async.wait_group %0;\n" :: "n"(N)); }

#define LDSM_X4(r0,r1,r2,r3,addr) \
    asm volatile("ldmatrix.sync.aligned.m8n8.x4.shared.b16 {%0,%1,%2,%3}, [%4];\n" \
        : "=r"(r0), "=r"(r1), "=r"(r2), "=r"(r3) : "r"(addr))

#define LDSM_X4T(r0,r1,r2,r3,addr) \
    asm volatile("ldmatrix.sync.aligned.m8n8.x4.trans.shared.b16 {%0,%1,%2,%3}, [%4];\n" \
        : "=r"(r0), "=r"(r1), "=r"(r2), "=r"(r3) : "r"(addr))

__device__ __forceinline__ void store_half4(__half* p, float a, float b, float c, float d)
{
    __half2 h01 = __floats2half2_rn(a, b);
    __half2 h23 = __floats2half2_rn(c, d);
    uint2 u;
    u.x = *reinterpret_cast<unsigned*>(&h01);
    u.y = *reinterpret_cast<unsigned*>(&h23);
    *reinterpret_cast<uint2*>(p) = u;
}

// ---------------- merged weight prep (single launch) ----------------
__global__ void prep_weights(const float* __restrict__ W_val, const float* __restrict__ W_out,
                             const float* __restrict__ W_ff1, const float* __restrict__ W_ff2,
                             const float* __restrict__ W_off, const float* __restrict__ W_attn,
                             const float* __restrict__ b_off, const float* __restrict__ b_attn)
{
    const int nVal = NLAYERS_*E_*E_;
    const int nFf  = NLAYERS_*E_*DF_;
    const int nQa  = NLAYERS_*E_*512;
    int i = blockIdx.x * blockDim.x + threadIdx.x;
    if (i < nVal) { g_Wval[i] = __float2half_rn(W_val[i]); return; }
    i -= nVal;
    if (i < nVal) { g_Wout[i] = __float2half_rn(W_out[i]); return; }
    i -= nVal;
    if (i < nFf)  { g_Wff1[i] = __float2half_rn(W_ff1[i]); return; }
    i -= nFf;
    if (i < nFf)  { g_Wff2[i] = __float2half_rn(W_ff2[i]); return; }
    i -= nFf;
    if (i < nQa) {
        int l = i / (E_ * 512);
        int rem = i - l * E_ * 512;
        int k = rem >> 9;
        int c = rem & 511;
        float v = (c < 384) ? W_off[(size_t)l*E_*384 + k*384 + c]
                            : W_attn[(size_t)l*E_*128 + k*128 + (c - 384)];
        g_Wqa[i] = __float2half_rn(v);
        return;
    }
    i -= nQa;
    if (i < NLAYERS_ * 512) {
        int l = i >> 9;
        int c = i & 511;
        g_bqa[i] = (c < 384) ? b_off[l*384 + c] : b_attn[l*128 + (c - 384)];
    }
}
#define PREP_TOT (2*NLAYERS_*E_*E_ + 2*NLAYERS_*E_*DF_ + NLAYERS_*E_*512 + NLAYERS_*512)

// ---------------- coalesced transposing init (per level) ----------------
__global__ void init_t_kernel(const float* __restrict__ f, const float* __restrict__ p,
                              const float* __restrict__ le_row, int n, int s0)
{
    __shared__ float tf[32][33];
    __shared__ float tp[32][33];
    int i0 = blockIdx.x * 32;
    int e0 = blockIdx.y * 32;
    int b  = blockIdx.z;
    int tx = threadIdx.x, ty = threadIdx.y;

    int ig = i0 + tx;
    int eg = e0 + ty;
    if (ig < n) {
        size_t src = (size_t)(b*E_ + eg) * n + ig;
        tf[ty][tx] = f[src];
        tp[ty][tx] = p[src];
    }
    __syncthreads();

    int iw = i0 + ty;
    int ew = e0 + tx;
    if (iw < n) {
        size_t dst = (size_t)(b*S_ + s0 + iw) * E_ + ew;
        float xv = tf[tx][ty];
        float pv = tp[tx][ty] + le_row[ew];
        g_x[dst]   = xv;
        g_xh[dst]  = __float2half_rn(xv);
        g_pos[dst] = pv;
        g_qh[dst]  = __float2half_rn(xv + pv);
    }
}

// ---------------- fp16 tensor-core GEMM (m16n8k16), BK=64, 3-stage cp.async --
// C = A[M,K](fp16) @ W[K,N](fp16) + bias(fp32)
// mode: 0 = fp32 out, 1 = relu + fp16 out, 2 = fp16 out
template<int BMt, int BNt>
__global__ void __launch_bounds__(256, (BMt==64 ? 4 : 2))
mma_gemm(const __half* __restrict__ A, const __half* __restrict__ W,
         const float* __restrict__ bias, void* __restrict__ Cv,
         int M, int N, int K, int mode)
{
    constexpr int MI   = BMt/32;         // m16 tiles per warp (warp m = BMt/2)
    constexpr int NI   = BNt/32;         // n8 tiles per warp (warp n = BNt/4)
    constexpr int ACH  = BMt/32;         // A 16B chunks per thread (BM*8/256)
    constexpr int BCH  = BNt/32;         // B chunks per thread (64*(BN/8)/256)
    constexpr int BCPR = BNt/8;          // B chunks per k-row
    constexpr int ASTR = 72;             // halves per A row (144B: 16i mod 128 distinct)
    constexpr int BSTR = BNt + 8;        // halves per B row
    constexpr int A_FL = BMt*ASTR;       // halves
    constexpr int B_FL = 64*BSTR;        // halves
    constexpr int STG  = A_FL + B_FL;    // halves per stage

    extern __shared__ __half smh[];

    int tid  = threadIdx.x;
    int lane = tid & 31;
    int wid  = tid >> 5;
    int bm = blockIdx.y * BMt;
    int bn = blockIdx.x * BNt;
    int wm = (wid >> 2) * (BMt/2);
    int wn = (wid & 3) * (BNt/4);
    int q = lane >> 2;
    int r = lane & 3;

    float acc[MI][NI][4];
    #pragma unroll
    for (int mi = 0; mi < MI; mi++)
        #pragma unroll
        for (int ni = 0; ni < NI; ni++)
            #pragma unroll
            for (int j = 0; j < 4; j++) acc[mi][ni][j] = 0.f;

    // cp.async maps: A rows of 64 halves = 8 chunks; B 64 rows of BNt halves
    int arow[ACH], ac8[ACH]; bool aval[ACH];
    #pragma unroll
    for (int i = 0; i < ACH; i++) {
        int idx = tid + i*256; arow[i] = idx >> 3; ac8[i] = idx & 7;
        aval[i] = (bm + arow[i]) < M;
    }
    int brow[BCH], bc8[BCH];
    #pragma unroll
    for (int i = 0; i < BCH; i++) { int idx = tid + i*256; brow[i] = idx / BCPR; bc8[i] = idx % BCPR; }

    int nkt = K / 64;

    unsigned smem_u32 = (unsigned)__cvta_generic_to_shared(smh);
    unsigned a_lane_off = (unsigned)(((lane & 15) * ASTR + (lane >> 4) * 8) * 2);
    unsigned b_lane_off = (unsigned)(((((lane >> 3) & 1) * 8 + (lane & 7)) * BSTR
                                      + (lane >> 4) * 8) * 2);

    auto load_stage = [&](int slot, int kg) {
        __half* As = smh + slot*STG;
        __half* Bs = As + A_FL;
        #pragma unroll
        for (int i = 0; i < ACH; i++)
            cp_async16(As + arow[i]*ASTR + ac8[i]*8,
                       A + (size_t)(aval[i] ? (bm + arow[i]) : 0) * K + kg + ac8[i]*8, aval[i]);
        #pragma unroll
        for (int i = 0; i < BCH; i++)
            cp_async16(Bs + brow[i]*BSTR + bc8[i]*8,
                       W + (size_t)(kg + brow[i]) * N + bn + bc8[i]*8, true);
    };

    load_stage(0, 0);
    cp_commit();
    if (nkt > 1) load_stage(1, 64);
    cp_commit();

    for (int kt = 0; kt < nkt; kt++) {
        int st = kt % 3;
        if (kt + 2 < nkt) load_stage((kt + 2) % 3, (kt + 2) * 64);
        cp_commit();
        cp_wait<2>();
        __syncthreads();

        unsigned abase = smem_u32 + (unsigned)(st*STG)*2u + (unsigned)(wm*ASTR)*2u + a_lane_off;
        unsigned bbase = smem_u32 + (unsigned)((st*STG + A_FL))*2u + (unsigned)wn*2u + b_lane_off;

        #pragma unroll
        for (int ks = 0; ks < 4; ks++) {
            unsigned af[MI][4], bf[NI][2];
            #pragma unroll
            for (int mi = 0; mi < MI; mi++) {
                LDSM_X4(af[mi][0], af[mi][1], af[mi][2], af[mi][3],
                        abase + (unsigned)((mi*16*ASTR + ks*16)*2));
            }
            #pragma unroll
            for (int nb = 0; nb < NI/2; nb++) {
                LDSM_X4T(bf[2*nb][0], bf[2*nb][1], bf[2*nb+1][0], bf[2*nb+1][1],
                         bbase + (unsigned)((ks*16*BSTR + nb*16)*2));
            }
            #pragma unroll
            for (int mi = 0; mi < MI; mi++)
                #pragma unroll
                for (int ni = 0; ni < NI; ni++)
                    mma_f16(acc[mi][ni], af[mi], bf[ni]);
        }
        __syncthreads();
    }

    // epilogue
    #pragma unroll
    for (int mi = 0; mi < MI; mi++) {
        #pragma unroll
        for (int ni = 0; ni < NI; ni++) {
            int row = bm + wm + mi*16 + q;
            int col = bn + wn + ni*8 + r*2;
            float bx = bias[col], by = bias[col+1];
            float v0 = acc[mi][ni][0] + bx;
            float v1 = acc[mi][ni][1] + by;
            float v2 = acc[mi][ni][2] + bx;
            float v3 = acc[mi][ni][3] + by;
            if (mode == 1) {
                v0 = fmaxf(v0, 0.f); v1 = fmaxf(v1, 0.f);
                v2 = fmaxf(v2, 0.f); v3 = fmaxf(v3, 0.f);
            }
            if (mode == 0) {
                float* C = (float*)Cv;
                if (row < M)
                    *(float2*)&C[(size_t)row * N + col] = make_float2(v0, v1);
                if (row + 8 < M)
                    *(float2*)&C[(size_t)(row + 8) * N + col] = make_float2(v2, v3);
            } else {
                __half* Ch = (__half*)Cv;
                if (row < M)
                    *(__half2*)&Ch[(size_t)row * N + col] = __floats2half2_rn(v0, v1);
                if (row + 8 < M)
                    *(__half2*)&Ch[(size_t)(row + 8) * N + col] = __floats2half2_rn(v2, v3);
            }
        }
    }
}

// ---------------- deformable sampling, fp16 value, half4 loads ----------------
__global__ void sample_kernel()
{
    int warpIdx = (blockIdx.x * blockDim.x + threadIdx.x) >> 5;
    int lane  = threadIdx.x & 31;
    if (warpIdx >= M_ * NH_) return;
    int h  = warpIdx / M_;
    int bs = warpIdx - h * M_;
    int b  = bs / S_;
    int s  = bs % S_;
    int eg = lane & 7;
    int pg = lane >> 3;

    int lvl_q, iq;
    if (s < 9216)       { lvl_q = 0; iq = s;         }
    else if (s < 10368) { lvl_q = 1; iq = s - 9216;  }
    else if (s < 10512) { lvl_q = 2; iq = s - 10368; }
    else                { lvl_q = 3; iq = s - 10512; }
    int Wq = c_LW[lvl_q], Hq = c_LH[lvl_q], Dq = c_LD[lvl_q];
    int xq = iq % Wq;
    int t  = iq / Wq;
    int yq = t % Hq;
    int zq = t / Hq;
    float rx = (xq + 0.5f) / (float)Wq;
    float ry = (yq + 0.5f) / (float)Hq;
    float rz = (zq + 0.5f) / (float)Dq;

    const float4* lg4 = (const float4*)(g_oa + (size_t)bs * 512 + 384 + h * 16);
    float lv[16];
    {
        float4 v0 = lg4[0], v1 = lg4[1], v2 = lg4[2], v3 = lg4[3];
        lv[0]=v0.x; lv[1]=v0.y; lv[2]=v0.z; lv[3]=v0.w;
        lv[4]=v1.x; lv[5]=v1.y; lv[6]=v1.z; lv[7]=v1.w;
        lv[8]=v2.x; lv[9]=v2.y; lv[10]=v2.z; lv[11]=v2.w;
        lv[12]=v3.x; lv[13]=v3.y; lv[14]=v3.z; lv[15]=v3.w;
    }
    float mx = -1e30f;
    #pragma unroll
    for (int j = 0; j < 16; j++) mx = fmaxf(mx, lv[j]);
    float ssum = 0.f;
    #pragma unroll
    for (int j = 0; j < 16; j++) { lv[j] = __expf(lv[j] - mx); ssum += lv[j]; }
    float inv = 1.f / ssum;

    const float* offp = g_oa + (size_t)bs * 512 + h * (NL_*NP_*3);

    const int LDc[4]  = {4, 2, 1, 1};
    const int LHc[4]  = {48, 24, 12, 6};
    const int LWc[4]  = {48, 24, 12, 6};
    const int LS0c[4] = {0, 9216, 10368, 10512};

    float4 acc = make_float4(0.f, 0.f, 0.f, 0.f);

    #pragma unroll
    for (int lvl = 0; lvl < 4; lvl++) {
        const int Dl = LDc[lvl], Hl = LHc[lvl], Wl = LWc[lvl];
        const __half* vb = g_valh + ((size_t)b * S_ + LS0c[lvl]) * E_ + h * HD_ + eg * 4;

        float aw = lv[lvl*4 + pg] * inv;
        float ox = offp[lvl*12 + pg*3 + 0];
        float oy = offp[lvl*12 + pg*3 + 1];
        float oz = offp[lvl*12 + pg*3 + 2];
        float cx = rx * (float)Wl + ox - 0.5f;
        float cy = ry * (float)Hl + oy - 0.5f;
        float cz = rz * (float)Dl + oz - 0.5f;
        float xf = floorf(cx), yf = floorf(cy), zf = floorf(cz);
        float fx = cx - xf, fy = cy - yf, fz = cz - zf;
        int x0 = (int)xf, y0 = (int)yf, z0 = (int)zf;

        #pragma unroll
        for (int dz = 0; dz < 2; dz++) {
            int iz = z0 + dz;
            float wz = dz ? fz : 1.f - fz;
            bool vz = (iz >= 0) & (iz < Dl);
            int cz_i = min(max(iz, 0), Dl - 1);
            #pragma unroll
            for (int dy = 0; dy < 2; dy++) {
                int iy = y0 + dy;
                float wy = dy ? fy : 1.f - fy;
                bool vy = (iy >= 0) & (iy < Hl);
                int cy_i = min(max(iy, 0), Hl - 1);
                #pragma unroll
                for (int dx = 0; dx < 2; dx++) {
                    int ix = x0 + dx;
                    float wx = dx ? fx : 1.f - fx;
                    bool vx = (ix >= 0) & (ix < Wl);
                    int cx_i = min(max(ix, 0), Wl - 1);
                    float wgt = (vz & vy & vx) ? (aw * wx * wy * wz) : 0.f;
                    int idx = (cz_i*Hl + cy_i)*Wl + cx_i;
                    uint2 raw = *(const uint2*)(vb + (size_t)idx * E_);
                    __half2 h0 = *reinterpret_cast<const __half2*>(&raw.x);
                    __half2 h1 = *reinterpret_cast<const __half2*>(&raw.y);
                    float2 f0 = __half22float2(h0);
                    float2 f1 = __half22float2(h1);
                    acc.x += wgt * f0.x;
                    acc.y += wgt * f0.y;
                    acc.z += wgt * f1.x;
                    acc.w += wgt * f1.y;
                }
            }
        }
    }

    #pragma unroll
    for (int o = 8; o <= 16; o <<= 1) {
        acc.x += __shfl_xor_sync(0xFFFFFFFFu, acc.x, o);
        acc.y += __shfl_xor_sync(0xFFFFFFFFu, acc.y, o);
        acc.z += __shfl_xor_sync(0xFFFFFFFFu, acc.z, o);
        acc.w += __shfl_xor_sync(0xFFFFFFFFu, acc.w, o);
    }

    if (lane < 8) {
        store_half4(g_samh + (size_t)bs * E_ + h * HD_ + lane * 4,
                    acc.x, acc.y, acc.z, acc.w);
    }
}

// ---------------- fused residual + LayerNorm: warp-per-row, 8 rows/block ----
__global__ void __launch_bounds__(256)
ln8_kernel(const float* __restrict__ x, const float* __restrict__ r,
           const float* __restrict__ g, const float* __restrict__ be,
           float* __restrict__ out, __half* __restrict__ outh,
           const float* __restrict__ pos, __half* __restrict__ qouth)
{
    int wid  = threadIdx.x >> 5;
    int lane = threadIdx.x & 31;
    int row  = blockIdx.x * 8 + wid;   // M_ = 21096 = 2637 * 8
    size_t base = (size_t)row * E_;
    int c0 = lane * 4;
    int c1 = 128 + lane * 4;

    float4 xa = *(const float4*)(x + base + c0);
    float4 xb = *(const float4*)(x + base + c1);
    float4 ra = *(const float4*)(r + base + c0);
    float4 rb = *(const float4*)(r + base + c1);
    float4 va = make_float4(xa.x+ra.x, xa.y+ra.y, xa.z+ra.z, xa.w+ra.w);
    float4 vb = make_float4(xb.x+rb.x, xb.y+rb.y, xb.z+rb.z, xb.w+rb.w);

    float ssum = va.x+va.y+va.z+va.w + vb.x+vb.y+vb.z+vb.w;
    #pragma unroll
    for (int o = 16; o > 0; o >>= 1) ssum += __shfl_xor_sync(0xFFFFFFFFu, ssum, o);
    float mean = ssum * (1.f / E_);

    float4 da = make_float4(va.x-mean, va.y-mean, va.z-mean, va.w-mean);
    float4 db = make_float4(vb.x-mean, vb.y-mean, vb.z-mean, vb.w-mean);
    float vsum = da.x*da.x+da.y*da.y+da.z*da.z+da.w*da.w
               + db.x*db.x+db.y*db.y+db.z*db.z+db.w*db.w;
    #pragma unroll
    for (int o = 16; o > 0; o >>= 1) vsum += __shfl_xor_sync(0xFFFFFFFFu, vsum, o);
    float inv = rsqrtf(vsum * (1.f / E_) + 1e-5f);

    float4 ga = *(const float4*)(g + c0);
    float4 gb = *(const float4*)(g + c1);
    float4 ba = *(const float4*)(be + c0);
    float4 bb = *(const float4*)(be + c1);

    float4 ya = make_float4(da.x*inv*ga.x + ba.x, da.y*inv*ga.y + ba.y,
                            da.z*inv*ga.z + ba.z, da.w*inv*ga.w + ba.w);
    float4 yb = make_float4(db.x*inv*gb.x + bb.x, db.y*inv*gb.y + bb.y,
                            db.z*inv*gb.z + bb.z, db.w*inv*gb.w + bb.w);

    *(float4*)(out + base + c0) = ya;
    *(float4*)(out + base + c1) = yb;

    if (outh) {
        store_half4(outh + base + c0, ya.x, ya.y, ya.z, ya.w);
        store_half4(outh + base + c1, yb.x, yb.y, yb.z, yb.w);
    }
    if (qouth) {
        float4 pa = *(const float4*)(pos + base + c0);
        float4 pb = *(const float4*)(pos + base + c1);
        store_half4(qouth + base + c0, ya.x + pa.x, ya.y + pa.y, ya.z + pa.z, ya.w + pa.w);
        store_half4(qouth + base + c1, yb.x + pb.x, yb.y + pb.y, yb.z + pb.z, yb.w + pb.w);
    }
}

// ---------------- host launcher ----------------
// smem bytes = 3 * (BM*72 + 64*(BN+8)) * 2
#define SMEM128 (3*(128*72 + 64*136)*2)   // 107520
#define SMEM64  (3*(64*72 + 64*72)*2)     // 55296

extern "C" void kernel_launch(void* const* d_in, const int* in_sizes, int n_in,
                              void* d_out, int out_size)
{
    (void)in_sizes; (void)n_in; (void)out_size;
    const float* f0 = (const float*)d_in[0];
    const float* p0 = (const float*)d_in[1];
    const float* f1 = (const float*)d_in[2];
    const float* p1 = (const float*)d_in[3];
    const float* f2 = (const float*)d_in[4];
    const float* p2 = (const float*)d_in[5];
    const float* f3 = (const float*)d_in[6];
    const float* p3 = (const float*)d_in[7];
    const float* le = (const float*)d_in[8];
    const float* W_off  = (const float*)d_in[9];
    const float* b_off  = (const float*)d_in[10];
    const float* W_attn = (const float*)d_in[11];
    const float* b_attn = (const float*)d_in[12];
    const float* W_val  = (const float*)d_in[13];
    const float* b_val  = (const float*)d_in[14];
    const float* W_out  = (const float*)d_in[15];
    const float* b_out  = (const float*)d_in[16];
    const float* ln1_g  = (const float*)d_in[17];
    const float* ln1_b  = (const float*)d_in[18];
    const float* W_ff1  = (const float*)d_in[19];
    const float* b_ff1  = (const float*)d_in[20];
    const float* W_ff2  = (const float*)d_in[21];
    const float* b_ff2  = (const float*)d_in[22];
    const float* ln2_g  = (const float*)d_in[23];
    const float* ln2_b  = (const float*)d_in[24];

    float  *px, *ppos, *ptmp, *poa, *pbqa;
    __half *pxh, *pqh, *pvalh, *psamh, *phidh;
    __half *pWval, *pWqa, *pWout, *pWff1, *pWff2;
    cudaGetSymbolAddress((void**)&px,    g_x);
    cudaGetSymbolAddress((void**)&pxh,   g_xh);
    cudaGetSymbolAddress((void**)&ppos,  g_pos);
    cudaGetSymbolAddress((void**)&pqh,   g_qh);
    cudaGetSymbolAddress((void**)&pvalh, g_valh);
    cudaGetSymbolAddress((void**)&psamh, g_samh);
    cudaGetSymbolAddress((void**)&ptmp,  g_tmp);
    cudaGetSymbolAddress((void**)&phidh, g_hidh);
    cudaGetSymbolAddress((void**)&poa,   g_oa);
    cudaGetSymbolAddress((void**)&pWval, g_Wval);
    cudaGetSymbolAddress((void**)&pWqa,  g_Wqa);
    cudaGetSymbolAddress((void**)&pWout, g_Wout);
    cudaGetSymbolAddress((void**)&pWff1, g_Wff1);
    cudaGetSymbolAddress((void**)&pWff2, g_Wff2);
    cudaGetSymbolAddress((void**)&pbqa,  g_bqa);

    cudaFuncSetAttribute(mma_gemm<128,128>, cudaFuncAttributeMaxDynamicSharedMemorySize, SMEM128);
    cudaFuncSetAttribute(mma_gemm<64,64>,   cudaFuncAttributeMaxDynamicSharedMemorySize, SMEM64);

    // launch 1: merged weight prep
    prep_weights<<<(PREP_TOT + 255)/256, 256>>>(W_val, W_out, W_ff1, W_ff2,
                                                W_off, W_attn, b_off, b_attn);

    // launches 2-5: transposing init, one per level
    {
        dim3 blk(32, 32);
        init_t_kernel<<<dim3(288, 8, B_), blk>>>(f0, p0, le + 0*E_, 9216, 0);
        init_t_kernel<<<dim3( 36, 8, B_), blk>>>(f1, p1, le + 1*E_, 1152, 9216);
        init_t_kernel<<<dim3(  5, 8, B_), blk>>>(f2, p2, le + 2*E_,  144, 10368);
        init_t_kernel<<<dim3(  2, 8, B_), blk>>>(f3, p3, le + 3*E_,   36, 10512);
    }

    const int GM64  = (M_ + 63) / 64;    // 330
    const int GM128 = (M_ + 127) / 128;  // 165
    const int LNB   = M_ / 8;            // 2637

    for (int l = 0; l < NLAYERS_; l++) {
        // value proj -> fp16 out
        mma_gemm<64,64><<<dim3(E_/64, GM64), 256, SMEM64>>>(pxh, pWval + (size_t)l*E_*E_,
                                           b_val + l*E_, pvalh, M_, E_, E_, 2);
        // offsets + attn logits -> fp32 out
        mma_gemm<128,128><<<dim3(512/128, GM128), 256, SMEM128>>>(pqh, pWqa + (size_t)l*E_*512,
                                            pbqa + l*512, poa, M_, 512, E_, 0);

        sample_kernel<<<(M_ * NH_ * 32) / 256, 256>>>();

        // out proj: A = sampler fp16, fp32 out
        mma_gemm<64,64><<<dim3(E_/64, GM64), 256, SMEM64>>>(psamh, pWout + (size_t)l*E_*E_,
                                           b_out + l*E_, ptmp, M_, E_, E_, 0);
        ln8_kernel<<<LNB, 256>>>(px, ptmp, ln1_g + l*E_, ln1_b + l*E_, px, pxh,
                                 (const float*)0, (__half*)0);

        // ff1: relu + fp16 out
        mma_gemm<128,128><<<dim3(DF_/128, GM128), 256, SMEM128>>>(pxh, pWff1 + (size_t)l*E_*DF_,
                                            b_ff1 + l*DF_, phidh, M_, DF_, E_, 1);
        // ff2: A = hid fp16, fp32 out
        mma_gemm<64,64><<<dim3(E_/64, GM64), 256, SMEM64>>>(phidh, pWff2 + (size_t)l*DF_*E_,
                                           b_ff2 + l*E_, ptmp, M_, E_, DF_, 0);

        if (l == NLAYERS_ - 1) {
            ln8_kernel<<<LNB, 256>>>(px, ptmp, ln2_g + l*E_, ln2_b + l*E_,
                                     (float*)d_out, (__half*)0, (const float*)0, (__half*)0);
        } else {
            ln8_kernel<<<LNB, 256>>>(px, ptmp, ln2_g + l*E_, ln2_b + l*E_,
                                     px, pxh, ppos, pqh);
        }
    }
}